// round 1
// baseline (speedup 1.0000x reference)
#include <cuda_runtime.h>
#include <cuda_bf16.h>
#include <cstdio>

// Problem constants
#define BATCH 8
#define SEQ   512
#define DIM   768
#define HEADS 12
#define DHEAD 64
#define ROWS  (BATCH * SEQ)        // 4096
#define MAT   (ROWS * DIM)         // 3145728 elements per [B,S,D] tensor

// ---------------------------------------------------------------------------
// Scratch: 12 [B,S,D] fp32 buffers (q,k,v,qm,km,vm,app,amp,amm,apm,c1,c2)
// ---------------------------------------------------------------------------
__device__ float g_scratch[12ULL * MAT];

// ---------------------------------------------------------------------------
// Generic SGEMM with bias and optional dual-A (for concat @ Wfc):
//   C[M,N] = A1[M,K1] @ W[0:K1, N] + A2[M,K2] @ W[K1:K1+K2, N] + bias[N]
// Tile: 64x64, BK=16, 256 threads, 4x4 per thread.
// M=4096, N=768 divisible by 64; K divisible by 16. No bounds checks.
// ---------------------------------------------------------------------------
__global__ __launch_bounds__(256) void sgemm_bias(
    const float* __restrict__ A1, const float* __restrict__ A2,
    const float* __restrict__ W, const float* __restrict__ bias,
    float* __restrict__ C, int N, int K1, int K2)
{
    __shared__ float As[16][64];   // [k][m]
    __shared__ float Bs[16][64];   // [k][n]

    const int tid = threadIdx.x;
    const int tx = tid & 15;       // n sub-tile
    const int ty = tid >> 4;       // m sub-tile
    const int row0 = blockIdx.y * 64;
    const int col0 = blockIdx.x * 64;

    float acc[4][4] = {};
    const int Ktot = K1 + K2;

    for (int kt = 0; kt < Ktot; kt += 16) {
        const float* A;
        int kc, lda;
        if (kt < K1) { A = A1; kc = kt;      lda = K1; }
        else         { A = A2; kc = kt - K1; lda = K2; }

        // Load A tile (64 rows x 16 cols), transpose into As[k][m]
        {
            int r  = tid >> 2;          // 0..63
            int c4 = (tid & 3) * 4;     // 0,4,8,12
            float4 v = *reinterpret_cast<const float4*>(&A[(size_t)(row0 + r) * lda + kc + c4]);
            As[c4 + 0][r] = v.x; As[c4 + 1][r] = v.y;
            As[c4 + 2][r] = v.z; As[c4 + 3][r] = v.w;
        }
        // Load B tile (16 rows x 64 cols) directly
        {
            int r  = tid >> 4;          // 0..15
            int c4 = (tid & 15) * 4;    // 0..60
            *reinterpret_cast<float4*>(&Bs[r][c4]) =
                *reinterpret_cast<const float4*>(&W[(size_t)(kt + r) * N + col0 + c4]);
        }
        __syncthreads();

        #pragma unroll
        for (int k = 0; k < 16; k++) {
            float a[4], b[4];
            #pragma unroll
            for (int i = 0; i < 4; i++) a[i] = As[k][ty * 4 + i];
            #pragma unroll
            for (int j = 0; j < 4; j++) b[j] = Bs[k][tx * 4 + j];
            #pragma unroll
            for (int i = 0; i < 4; i++)
                #pragma unroll
                for (int j = 0; j < 4; j++)
                    acc[i][j] += a[i] * b[j];
        }
        __syncthreads();
    }

    #pragma unroll
    for (int i = 0; i < 4; i++) {
        int r = row0 + ty * 4 + i;
        #pragma unroll
        for (int j = 0; j < 4; j++) {
            int c = col0 + tx * 4 + j;
            C[(size_t)r * N + c] = acc[i][j] + bias[c];
        }
    }
}

// ---------------------------------------------------------------------------
// Flash-style attention for one (batch, head, 64-row q-tile).
// Q,K,V,O all [B,S,D] fp32, head h occupies columns h*64..h*64+63.
// Online softmax; K tiles of 64 streamed; smem buffers transposed so all
// compute-phase reads are row-contiguous (conflict-free).
// 256 threads: 16x16 grid of 4x4 register tiles.
// ---------------------------------------------------------------------------
__global__ __launch_bounds__(256) void attn_kernel(
    const float* __restrict__ Q, const float* __restrict__ K,
    const float* __restrict__ V, float* __restrict__ O)
{
    __shared__ float QsT[64][68];   // [d][qrow]
    __shared__ float KVs[64][68];   // K phase: [d][kcol]; V phase: [krow][d]
    __shared__ float PsT[64][68];   // [krow][qrow]

    const int tid = threadIdx.x;
    const int tx = tid & 15;
    const int ty = tid >> 4;
    const int qt = blockIdx.x;      // 0..7
    const int h  = blockIdx.y;      // 0..11
    const int b  = blockIdx.z;      // 0..7

    const float* Qb = Q + ((size_t)b * SEQ + qt * 64) * DIM + h * DHEAD;
    const float* Kb = K + (size_t)b * SEQ * DIM + h * DHEAD;
    const float* Vb = V + (size_t)b * SEQ * DIM + h * DHEAD;

    // Load Q tile (64x64), transposed: QsT[d][row]
    #pragma unroll
    for (int lo = 0; lo < 4; lo++) {
        int idx = tid + lo * 256;
        int r = idx >> 4;
        int c4 = (idx & 15) * 4;
        float4 v = *reinterpret_cast<const float4*>(&Qb[(size_t)r * DIM + c4]);
        QsT[c4 + 0][r] = v.x; QsT[c4 + 1][r] = v.y;
        QsT[c4 + 2][r] = v.z; QsT[c4 + 3][r] = v.w;
    }

    float m[4], l[4], acc[4][4] = {};
    #pragma unroll
    for (int i = 0; i < 4; i++) { m[i] = -1e30f; l[i] = 0.f; }

    for (int kt = 0; kt < SEQ / 64; kt++) {
        // Load K tile transposed: KVs[d][kcol]
        #pragma unroll
        for (int lo = 0; lo < 4; lo++) {
            int idx = tid + lo * 256;
            int j = idx >> 4;
            int c4 = (idx & 15) * 4;
            float4 v = *reinterpret_cast<const float4*>(&Kb[(size_t)(kt * 64 + j) * DIM + c4]);
            KVs[c4 + 0][j] = v.x; KVs[c4 + 1][j] = v.y;
            KVs[c4 + 2][j] = v.z; KVs[c4 + 3][j] = v.w;
        }
        __syncthreads();

        // Scores s[i][j] = sum_d Q[row_i][d] * K[col_j][d]
        float s[4][4] = {};
        #pragma unroll 8
        for (int d = 0; d < 64; d++) {
            float a[4], bb[4];
            #pragma unroll
            for (int i = 0; i < 4; i++) a[i] = QsT[d][ty * 4 + i];
            #pragma unroll
            for (int j = 0; j < 4; j++) bb[j] = KVs[d][tx * 4 + j];
            #pragma unroll
            for (int i = 0; i < 4; i++)
                #pragma unroll
                for (int j = 0; j < 4; j++)
                    s[i][j] += a[i] * bb[j];
        }
        __syncthreads();   // done reading KVs (K); will be overwritten by V

        // Online softmax (scale 1/sqrt(64) = 0.125)
        #pragma unroll
        for (int i = 0; i < 4; i++) {
            #pragma unroll
            for (int j = 0; j < 4; j++) s[i][j] *= 0.125f;

            float rm = fmaxf(fmaxf(s[i][0], s[i][1]), fmaxf(s[i][2], s[i][3]));
            #pragma unroll
            for (int o = 8; o >= 1; o >>= 1)
                rm = fmaxf(rm, __shfl_xor_sync(0xffffffffu, rm, o, 16));

            float mn = fmaxf(m[i], rm);
            float corr = __expf(m[i] - mn);
            m[i] = mn;

            float rs = 0.f;
            #pragma unroll
            for (int j = 0; j < 4; j++) {
                s[i][j] = __expf(s[i][j] - mn);
                rs += s[i][j];
            }
            #pragma unroll
            for (int o = 8; o >= 1; o >>= 1)
                rs += __shfl_xor_sync(0xffffffffu, rs, o, 16);

            l[i] = l[i] * corr + rs;
            #pragma unroll
            for (int c = 0; c < 4; c++) acc[i][c] *= corr;
        }

        // Write P transposed: PsT[kcol][qrow]
        #pragma unroll
        for (int i = 0; i < 4; i++)
            #pragma unroll
            for (int j = 0; j < 4; j++)
                PsT[tx * 4 + j][ty * 4 + i] = s[i][j];

        // Load V tile natural: KVs[krow][d]  (row stride 68 keeps 16B alignment)
        #pragma unroll
        for (int lo = 0; lo < 4; lo++) {
            int idx = tid + lo * 256;
            int j = idx >> 4;
            int c4 = (idx & 15) * 4;
            *reinterpret_cast<float4*>(&KVs[j][c4]) =
                *reinterpret_cast<const float4*>(&Vb[(size_t)(kt * 64 + j) * DIM + c4]);
        }
        __syncthreads();

        // acc += P @ V
        #pragma unroll 8
        for (int j = 0; j < 64; j++) {
            float p[4], vv[4];
            #pragma unroll
            for (int i = 0; i < 4; i++) p[i] = PsT[j][ty * 4 + i];
            #pragma unroll
            for (int c = 0; c < 4; c++) vv[c] = KVs[j][tx * 4 + c];
            #pragma unroll
            for (int i = 0; i < 4; i++)
                #pragma unroll
                for (int c = 0; c < 4; c++)
                    acc[i][c] += p[i] * vv[c];
        }
        __syncthreads();
    }

    // Epilogue: normalize and store (merged-heads layout [B,S,D])
    #pragma unroll
    for (int i = 0; i < 4; i++) {
        float inv = 1.f / l[i];
        int r = qt * 64 + ty * 4 + i;
        #pragma unroll
        for (int c = 0; c < 4; c++) {
            O[((size_t)b * SEQ + r) * DIM + h * DHEAD + tx * 4 + c] = acc[i][c] * inv;
        }
    }
}

// ---------------------------------------------------------------------------
// Host launcher
// ---------------------------------------------------------------------------
extern "C" void kernel_launch(void* const* d_in, const int* in_sizes, int n_in,
                              void* d_out, int out_size)
{
    const float* hs   = (const float*)d_in[0];
    const float* mol  = (const float*)d_in[1];
    const float* Wq   = (const float*)d_in[2];  const float* bq   = (const float*)d_in[3];
    const float* Wk   = (const float*)d_in[4];  const float* bk   = (const float*)d_in[5];
    const float* Wv   = (const float*)d_in[6];  const float* bv   = (const float*)d_in[7];
    const float* Wqm  = (const float*)d_in[8];  const float* bqm  = (const float*)d_in[9];
    const float* Wkm  = (const float*)d_in[10]; const float* bkm  = (const float*)d_in[11];
    const float* Wvm  = (const float*)d_in[12]; const float* bvm  = (const float*)d_in[13];
    const float* Wfc  = (const float*)d_in[14]; const float* bfc  = (const float*)d_in[15];
    const float* Wfcm = (const float*)d_in[16]; const float* bfcm = (const float*)d_in[17];
    const float* Wo   = (const float*)d_in[18]; const float* bo   = (const float*)d_in[19];
    const float* Wom  = (const float*)d_in[20]; const float* bom  = (const float*)d_in[21];

    float* outp = (float*)d_out;          // attn_prot
    float* outm = outp + (size_t)MAT;     // attn_mol

    float* base = nullptr;
    cudaGetSymbolAddress((void**)&base, g_scratch);
    float* q   = base + 0ULL  * MAT;
    float* k   = base + 1ULL  * MAT;
    float* v   = base + 2ULL  * MAT;
    float* qm  = base + 3ULL  * MAT;
    float* km  = base + 4ULL  * MAT;
    float* vm  = base + 5ULL  * MAT;
    float* app = base + 6ULL  * MAT;
    float* amp = base + 7ULL  * MAT;
    float* amm = base + 8ULL  * MAT;
    float* apm = base + 9ULL  * MAT;
    float* c1  = base + 10ULL * MAT;
    float* c2  = base + 11ULL * MAT;

    dim3 gGrid(DIM / 64, ROWS / 64);      // (12, 64)
    dim3 aGrid(SEQ / 64, HEADS, BATCH);   // (8, 12, 8)

    // 1) Six projections
    sgemm_bias<<<gGrid, 256>>>(hs,  nullptr, Wq,  bq,  q,  DIM, DIM, 0);
    sgemm_bias<<<gGrid, 256>>>(hs,  nullptr, Wk,  bk,  k,  DIM, DIM, 0);
    sgemm_bias<<<gGrid, 256>>>(hs,  nullptr, Wv,  bv,  v,  DIM, DIM, 0);
    sgemm_bias<<<gGrid, 256>>>(mol, nullptr, Wqm, bqm, qm, DIM, DIM, 0);
    sgemm_bias<<<gGrid, 256>>>(mol, nullptr, Wkm, bkm, km, DIM, DIM, 0);
    sgemm_bias<<<gGrid, 256>>>(mol, nullptr, Wvm, bvm, vm, DIM, DIM, 0);

    // 2) Four attentions (prot KV shared by q/qm; mol KV shared by qm/q)
    attn_kernel<<<aGrid, 256>>>(q,  k,  v,  app);
    attn_kernel<<<aGrid, 256>>>(qm, k,  v,  amp);
    attn_kernel<<<aGrid, 256>>>(qm, km, vm, amm);
    attn_kernel<<<aGrid, 256>>>(q,  km, vm, apm);

    // 3) Concat-FC (dual-A GEMM, K=1536 total)
    sgemm_bias<<<gGrid, 256>>>(app, amp, Wfc,  bfc,  c1, DIM, DIM, DIM);
    sgemm_bias<<<gGrid, 256>>>(amm, apm, Wfcm, bfcm, c2, DIM, DIM, DIM);

    // 4) Output projections
    sgemm_bias<<<gGrid, 256>>>(c1, nullptr, Wo,  bo,  outp, DIM, DIM, 0);
    sgemm_bias<<<gGrid, 256>>>(c2, nullptr, Wom, bom, outm, DIM, DIM, 0);
}

// round 2
// speedup vs baseline: 1.7761x; 1.7761x over previous
#include <cuda_runtime.h>
#include <cuda_bf16.h>
#include <cstdint>

// Problem constants
#define BATCH 8
#define SEQ   512
#define DIM   768
#define HEADS 12
#define DHEAD 64
#define ROWS  (BATCH * SEQ)        // 4096
#define MAT   (ROWS * DIM)         // 3145728 elements per [B,S,D] tensor

__device__ float g_scratch[12ULL * MAT];

__device__ __forceinline__ uint32_t f2tf32(float x) {
    uint32_t u;
    asm("cvt.rna.tf32.f32 %0, %1;" : "=r"(u) : "f"(x));
    return u;
}

// ---------------------------------------------------------------------------
// TF32 tensor-core GEMM with bias and optional dual-A (for concat @ Wfc):
//   C[M,N] = A1[M,K1] @ W[0:K1, N] + A2[M,K2] @ W[K1:, N] + bias[N]
// Block tile 128x128, BK=16, 256 threads = 8 warps (2m x 4n), warp tile 64x32.
// mma.sync.m16n8k8.tf32, double-buffered smem with register staging.
// ---------------------------------------------------------------------------
__global__ __launch_bounds__(256, 2) void gemm_tf32(
    const float* __restrict__ A1, const float* __restrict__ A2,
    const float* __restrict__ W, const float* __restrict__ bias,
    float* __restrict__ C, int N, int K1, int K2)
{
    __shared__ uint32_t As[2][128][20];   // [m][k], pad->conflict-free frag reads
    __shared__ uint32_t Bs[2][16][136];   // [k][n], pad 8 words

    const int tid  = threadIdx.x;
    const int lane = tid & 31;
    const int warp = tid >> 5;
    const int wm = (warp >> 2) * 64;      // warp M offset in tile
    const int wn = (warp & 3) * 32;       // warp N offset in tile
    const int row0 = blockIdx.y * 128;
    const int col0 = blockIdx.x * 128;
    const int Ktot = K1 + K2;

    float acc[4][4][4] = {};
    float4 ra[2], rb[2];

    auto ldg = [&](int kt) {
        const float* A; int kc, lda;
        if (kt < K1) { A = A1; kc = kt;      lda = K1; }
        else         { A = A2; kc = kt - K1; lda = K2; }
        #pragma unroll
        for (int lo = 0; lo < 2; lo++) {
            int idx = tid + lo * 256;
            int r = idx >> 2;              // 0..127
            int c4 = (idx & 3) * 4;        // 0,4,8,12
            ra[lo] = *reinterpret_cast<const float4*>(&A[(size_t)(row0 + r) * lda + kc + c4]);
        }
        #pragma unroll
        for (int lo = 0; lo < 2; lo++) {
            int idx = tid + lo * 256;
            int r = idx >> 5;              // 0..15
            int c4 = (idx & 31) * 4;       // 0..124
            rb[lo] = *reinterpret_cast<const float4*>(&W[(size_t)(kt + r) * N + col0 + c4]);
        }
    };
    auto sts = [&](int s) {
        #pragma unroll
        for (int lo = 0; lo < 2; lo++) {
            int idx = tid + lo * 256;
            int r = idx >> 2;
            int c4 = (idx & 3) * 4;
            uint4 u = make_uint4(f2tf32(ra[lo].x), f2tf32(ra[lo].y),
                                 f2tf32(ra[lo].z), f2tf32(ra[lo].w));
            *reinterpret_cast<uint4*>(&As[s][r][c4]) = u;
        }
        #pragma unroll
        for (int lo = 0; lo < 2; lo++) {
            int idx = tid + lo * 256;
            int r = idx >> 5;
            int c4 = (idx & 31) * 4;
            uint4 u = make_uint4(f2tf32(rb[lo].x), f2tf32(rb[lo].y),
                                 f2tf32(rb[lo].z), f2tf32(rb[lo].w));
            *reinterpret_cast<uint4*>(&Bs[s][r][c4]) = u;
        }
    };

    ldg(0); sts(0);
    __syncthreads();

    const int lr = lane >> 2;   // 0..7
    const int lc = lane & 3;    // 0..3
    int s = 0;
    for (int kt = 0; kt < Ktot; kt += 16) {
        const bool nxt = (kt + 16) < Ktot;
        if (nxt) ldg(kt + 16);

        #pragma unroll
        for (int ks = 0; ks < 16; ks += 8) {
            uint32_t a[4][4], b[4][2];
            #pragma unroll
            for (int mi = 0; mi < 4; mi++) {
                int m = wm + mi * 16;
                a[mi][0] = As[s][m + lr    ][ks + lc    ];
                a[mi][1] = As[s][m + lr + 8][ks + lc    ];
                a[mi][2] = As[s][m + lr    ][ks + lc + 4];
                a[mi][3] = As[s][m + lr + 8][ks + lc + 4];
            }
            #pragma unroll
            for (int ni = 0; ni < 4; ni++) {
                int n = wn + ni * 8;
                b[ni][0] = Bs[s][ks + lc    ][n + lr];
                b[ni][1] = Bs[s][ks + lc + 4][n + lr];
            }
            #pragma unroll
            for (int mi = 0; mi < 4; mi++)
                #pragma unroll
                for (int ni = 0; ni < 4; ni++) {
                    asm volatile(
                        "mma.sync.aligned.m16n8k8.row.col.f32.tf32.tf32.f32 "
                        "{%0,%1,%2,%3}, {%4,%5,%6,%7}, {%8,%9}, {%0,%1,%2,%3};"
                        : "+f"(acc[mi][ni][0]), "+f"(acc[mi][ni][1]),
                          "+f"(acc[mi][ni][2]), "+f"(acc[mi][ni][3])
                        : "r"(a[mi][0]), "r"(a[mi][1]), "r"(a[mi][2]), "r"(a[mi][3]),
                          "r"(b[ni][0]), "r"(b[ni][1]));
                }
        }

        if (nxt) sts(s ^ 1);
        __syncthreads();
        s ^= 1;
    }

    // Epilogue: c0/c1 at (row, col), c2/c3 at (row+8, col); cols consecutive pairs.
    #pragma unroll
    for (int mi = 0; mi < 4; mi++) {
        #pragma unroll
        for (int ni = 0; ni < 4; ni++) {
            int r = row0 + wm + mi * 16 + lr;
            int c = col0 + wn + ni * 8 + lc * 2;
            float b0 = bias[c], b1 = bias[c + 1];
            *reinterpret_cast<float2*>(&C[(size_t)r * N + c]) =
                make_float2(acc[mi][ni][0] + b0, acc[mi][ni][1] + b1);
            *reinterpret_cast<float2*>(&C[(size_t)(r + 8) * N + c]) =
                make_float2(acc[mi][ni][2] + b0, acc[mi][ni][3] + b1);
        }
    }
}

// ---------------------------------------------------------------------------
// Flash-style attention (unchanged from R1): fp32 SIMT, online softmax.
// One block per (b, h, 64-row q-tile); 256 threads, 4x4 register tiles.
// ---------------------------------------------------------------------------
__global__ __launch_bounds__(256) void attn_kernel(
    const float* __restrict__ Q, const float* __restrict__ K,
    const float* __restrict__ V, float* __restrict__ O)
{
    __shared__ float QsT[64][68];
    __shared__ float KVs[64][68];
    __shared__ float PsT[64][68];

    const int tid = threadIdx.x;
    const int tx = tid & 15;
    const int ty = tid >> 4;
    const int qt = blockIdx.x;
    const int h  = blockIdx.y;
    const int b  = blockIdx.z;

    const float* Qb = Q + ((size_t)b * SEQ + qt * 64) * DIM + h * DHEAD;
    const float* Kb = K + (size_t)b * SEQ * DIM + h * DHEAD;
    const float* Vb = V + (size_t)b * SEQ * DIM + h * DHEAD;

    #pragma unroll
    for (int lo = 0; lo < 4; lo++) {
        int idx = tid + lo * 256;
        int r = idx >> 4;
        int c4 = (idx & 15) * 4;
        float4 v = *reinterpret_cast<const float4*>(&Qb[(size_t)r * DIM + c4]);
        QsT[c4 + 0][r] = v.x; QsT[c4 + 1][r] = v.y;
        QsT[c4 + 2][r] = v.z; QsT[c4 + 3][r] = v.w;
    }

    float m[4], l[4], acc[4][4] = {};
    #pragma unroll
    for (int i = 0; i < 4; i++) { m[i] = -1e30f; l[i] = 0.f; }

    for (int kt = 0; kt < SEQ / 64; kt++) {
        #pragma unroll
        for (int lo = 0; lo < 4; lo++) {
            int idx = tid + lo * 256;
            int j = idx >> 4;
            int c4 = (idx & 15) * 4;
            float4 v = *reinterpret_cast<const float4*>(&Kb[(size_t)(kt * 64 + j) * DIM + c4]);
            KVs[c4 + 0][j] = v.x; KVs[c4 + 1][j] = v.y;
            KVs[c4 + 2][j] = v.z; KVs[c4 + 3][j] = v.w;
        }
        __syncthreads();

        float s[4][4] = {};
        #pragma unroll 8
        for (int d = 0; d < 64; d++) {
            float a[4], bb[4];
            #pragma unroll
            for (int i = 0; i < 4; i++) a[i] = QsT[d][ty * 4 + i];
            #pragma unroll
            for (int j = 0; j < 4; j++) bb[j] = KVs[d][tx * 4 + j];
            #pragma unroll
            for (int i = 0; i < 4; i++)
                #pragma unroll
                for (int j = 0; j < 4; j++)
                    s[i][j] += a[i] * bb[j];
        }
        __syncthreads();

        #pragma unroll
        for (int i = 0; i < 4; i++) {
            #pragma unroll
            for (int j = 0; j < 4; j++) s[i][j] *= 0.125f;

            float rm = fmaxf(fmaxf(s[i][0], s[i][1]), fmaxf(s[i][2], s[i][3]));
            #pragma unroll
            for (int o = 8; o >= 1; o >>= 1)
                rm = fmaxf(rm, __shfl_xor_sync(0xffffffffu, rm, o, 16));

            float mn = fmaxf(m[i], rm);
            float corr = __expf(m[i] - mn);
            m[i] = mn;

            float rs = 0.f;
            #pragma unroll
            for (int j = 0; j < 4; j++) {
                s[i][j] = __expf(s[i][j] - mn);
                rs += s[i][j];
            }
            #pragma unroll
            for (int o = 8; o >= 1; o >>= 1)
                rs += __shfl_xor_sync(0xffffffffu, rs, o, 16);

            l[i] = l[i] * corr + rs;
            #pragma unroll
            for (int c = 0; c < 4; c++) acc[i][c] *= corr;
        }

        #pragma unroll
        for (int i = 0; i < 4; i++)
            #pragma unroll
            for (int j = 0; j < 4; j++)
                PsT[tx * 4 + j][ty * 4 + i] = s[i][j];

        #pragma unroll
        for (int lo = 0; lo < 4; lo++) {
            int idx = tid + lo * 256;
            int j = idx >> 4;
            int c4 = (idx & 15) * 4;
            *reinterpret_cast<float4*>(&KVs[j][c4]) =
                *reinterpret_cast<const float4*>(&Vb[(size_t)(kt * 64 + j) * DIM + c4]);
        }
        __syncthreads();

        #pragma unroll 8
        for (int j = 0; j < 64; j++) {
            float p[4], vv[4];
            #pragma unroll
            for (int i = 0; i < 4; i++) p[i] = PsT[j][ty * 4 + i];
            #pragma unroll
            for (int c = 0; c < 4; c++) vv[c] = KVs[j][tx * 4 + c];
            #pragma unroll
            for (int i = 0; i < 4; i++)
                #pragma unroll
                for (int c = 0; c < 4; c++)
                    acc[i][c] += p[i] * vv[c];
        }
        __syncthreads();
    }

    #pragma unroll
    for (int i = 0; i < 4; i++) {
        float inv = 1.f / l[i];
        int r = qt * 64 + ty * 4 + i;
        #pragma unroll
        for (int c = 0; c < 4; c++) {
            O[((size_t)b * SEQ + r) * DIM + h * DHEAD + tx * 4 + c] = acc[i][c] * inv;
        }
    }
}

// ---------------------------------------------------------------------------
// Host launcher
// ---------------------------------------------------------------------------
extern "C" void kernel_launch(void* const* d_in, const int* in_sizes, int n_in,
                              void* d_out, int out_size)
{
    const float* hs   = (const float*)d_in[0];
    const float* mol  = (const float*)d_in[1];
    const float* Wq   = (const float*)d_in[2];  const float* bq   = (const float*)d_in[3];
    const float* Wk   = (const float*)d_in[4];  const float* bk   = (const float*)d_in[5];
    const float* Wv   = (const float*)d_in[6];  const float* bv   = (const float*)d_in[7];
    const float* Wqm  = (const float*)d_in[8];  const float* bqm  = (const float*)d_in[9];
    const float* Wkm  = (const float*)d_in[10]; const float* bkm  = (const float*)d_in[11];
    const float* Wvm  = (const float*)d_in[12]; const float* bvm  = (const float*)d_in[13];
    const float* Wfc  = (const float*)d_in[14]; const float* bfc  = (const float*)d_in[15];
    const float* Wfcm = (const float*)d_in[16]; const float* bfcm = (const float*)d_in[17];
    const float* Wo   = (const float*)d_in[18]; const float* bo   = (const float*)d_in[19];
    const float* Wom  = (const float*)d_in[20]; const float* bom  = (const float*)d_in[21];

    float* outp = (float*)d_out;
    float* outm = outp + (size_t)MAT;

    float* base = nullptr;
    cudaGetSymbolAddress((void**)&base, g_scratch);
    float* q   = base + 0ULL  * MAT;
    float* k   = base + 1ULL  * MAT;
    float* v   = base + 2ULL  * MAT;
    float* qm  = base + 3ULL  * MAT;
    float* km  = base + 4ULL  * MAT;
    float* vm  = base + 5ULL  * MAT;
    float* app = base + 6ULL  * MAT;
    float* amp = base + 7ULL  * MAT;
    float* amm = base + 8ULL  * MAT;
    float* apm = base + 9ULL  * MAT;
    float* c1  = base + 10ULL * MAT;
    float* c2  = base + 11ULL * MAT;

    dim3 gGrid(DIM / 128, ROWS / 128);    // (6, 32) = 192 blocks
    dim3 aGrid(SEQ / 64, HEADS, BATCH);   // (8, 12, 8)

    // 1) Six projections (TF32 tensor cores)
    gemm_tf32<<<gGrid, 256>>>(hs,  nullptr, Wq,  bq,  q,  DIM, DIM, 0);
    gemm_tf32<<<gGrid, 256>>>(hs,  nullptr, Wk,  bk,  k,  DIM, DIM, 0);
    gemm_tf32<<<gGrid, 256>>>(hs,  nullptr, Wv,  bv,  v,  DIM, DIM, 0);
    gemm_tf32<<<gGrid, 256>>>(mol, nullptr, Wqm, bqm, qm, DIM, DIM, 0);
    gemm_tf32<<<gGrid, 256>>>(mol, nullptr, Wkm, bkm, km, DIM, DIM, 0);
    gemm_tf32<<<gGrid, 256>>>(mol, nullptr, Wvm, bvm, vm, DIM, DIM, 0);

    // 2) Four attentions
    attn_kernel<<<aGrid, 256>>>(q,  k,  v,  app);
    attn_kernel<<<aGrid, 256>>>(qm, k,  v,  amp);
    attn_kernel<<<aGrid, 256>>>(qm, km, vm, amm);
    attn_kernel<<<aGrid, 256>>>(q,  km, vm, apm);

    // 3) Concat-FC (dual-A, K=1536)
    gemm_tf32<<<gGrid, 256>>>(app, amp, Wfc,  bfc,  c1, DIM, DIM, DIM);
    gemm_tf32<<<gGrid, 256>>>(amm, apm, Wfcm, bfcm, c2, DIM, DIM, DIM);

    // 4) Output projections
    gemm_tf32<<<gGrid, 256>>>(c1, nullptr, Wo,  bo,  outp, DIM, DIM, 0);
    gemm_tf32<<<gGrid, 256>>>(c2, nullptr, Wom, bom, outm, DIM, DIM, 0);
}

// round 3
// speedup vs baseline: 2.8628x; 1.6118x over previous
#include <cuda_runtime.h>
#include <cuda_bf16.h>
#include <cstdint>

#define BATCH 8
#define SEQ   512
#define DIM   768
#define HEADS 12
#define DHEAD 64
#define ROWS  (BATCH * SEQ)        // 4096
#define MAT   (ROWS * DIM)         // 3145728

__device__ float g_scratch[12ULL * MAT];

__device__ __forceinline__ uint32_t f2tf32(float x) {
    uint32_t u;
    asm("cvt.rna.tf32.f32 %0, %1;" : "=r"(u) : "f"(x));
    return u;
}

#define MMA_TF32(D, A, B0, B1)                                              \
    asm volatile(                                                           \
        "mma.sync.aligned.m16n8k8.row.col.f32.tf32.tf32.f32 "               \
        "{%0,%1,%2,%3}, {%4,%5,%6,%7}, {%8,%9}, {%0,%1,%2,%3};"             \
        : "+f"((D)[0]), "+f"((D)[1]), "+f"((D)[2]), "+f"((D)[3])            \
        : "r"((A)[0]), "r"((A)[1]), "r"((A)[2]), "r"((A)[3]),               \
          "r"(B0), "r"(B1))

// ---------------------------------------------------------------------------
// Batched TF32 GEMM: z selects one {A1,A2,W,bias,C,K1,K2} job.
//   C = A1[M,K1] @ W[0:K1,:] + A2[M,K2] @ W[K1:,:] + bias
// Block tile 128x128, BK=16, 256 thr = 8 warps (2x4), warp 64x32, dbl-buffered.
// ---------------------------------------------------------------------------
struct GB { const float* A1; const float* A2; const float* W; const float* bias;
            float* C; int K1; int K2; };
struct GBatch { GB g[6]; };

__global__ __launch_bounds__(256, 2) void gemm_tf32(GBatch batch)
{
    __shared__ uint32_t As[2][128][20];
    __shared__ uint32_t Bs[2][16][136];

    const GB gb = batch.g[blockIdx.z];
    const float* __restrict__ A1 = gb.A1;
    const float* __restrict__ A2 = gb.A2;
    const float* __restrict__ W  = gb.W;
    const int K1 = gb.K1, K2 = gb.K2;
    const int N = DIM;

    const int tid  = threadIdx.x;
    const int lane = tid & 31;
    const int warp = tid >> 5;
    const int wm = (warp >> 2) * 64;
    const int wn = (warp & 3) * 32;
    const int row0 = blockIdx.y * 128;
    const int col0 = blockIdx.x * 128;
    const int Ktot = K1 + K2;

    float acc[4][4][4] = {};
    float4 ra[2], rb[2];

    auto ldg = [&](int kt) {
        const float* A; int kc, lda;
        if (kt < K1) { A = A1; kc = kt;      lda = K1; }
        else         { A = A2; kc = kt - K1; lda = K2; }
        #pragma unroll
        for (int lo = 0; lo < 2; lo++) {
            int idx = tid + lo * 256;
            int r = idx >> 2, c4 = (idx & 3) * 4;
            ra[lo] = *reinterpret_cast<const float4*>(&A[(size_t)(row0 + r) * lda + kc + c4]);
        }
        #pragma unroll
        for (int lo = 0; lo < 2; lo++) {
            int idx = tid + lo * 256;
            int r = idx >> 5, c4 = (idx & 31) * 4;
            rb[lo] = *reinterpret_cast<const float4*>(&W[(size_t)(kt + r) * N + col0 + c4]);
        }
    };
    auto sts = [&](int s) {
        #pragma unroll
        for (int lo = 0; lo < 2; lo++) {
            int idx = tid + lo * 256;
            int r = idx >> 2, c4 = (idx & 3) * 4;
            uint4 u = make_uint4(f2tf32(ra[lo].x), f2tf32(ra[lo].y),
                                 f2tf32(ra[lo].z), f2tf32(ra[lo].w));
            *reinterpret_cast<uint4*>(&As[s][r][c4]) = u;
        }
        #pragma unroll
        for (int lo = 0; lo < 2; lo++) {
            int idx = tid + lo * 256;
            int r = idx >> 5, c4 = (idx & 31) * 4;
            uint4 u = make_uint4(f2tf32(rb[lo].x), f2tf32(rb[lo].y),
                                 f2tf32(rb[lo].z), f2tf32(rb[lo].w));
            *reinterpret_cast<uint4*>(&Bs[s][r][c4]) = u;
        }
    };

    ldg(0); sts(0);
    __syncthreads();

    const int lr = lane >> 2;
    const int lc = lane & 3;
    int s = 0;
    for (int kt = 0; kt < Ktot; kt += 16) {
        const bool nxt = (kt + 16) < Ktot;
        if (nxt) ldg(kt + 16);

        #pragma unroll
        for (int ks = 0; ks < 16; ks += 8) {
            uint32_t a[4][4], b[4][2];
            #pragma unroll
            for (int mi = 0; mi < 4; mi++) {
                int m = wm + mi * 16;
                a[mi][0] = As[s][m + lr    ][ks + lc    ];
                a[mi][1] = As[s][m + lr + 8][ks + lc    ];
                a[mi][2] = As[s][m + lr    ][ks + lc + 4];
                a[mi][3] = As[s][m + lr + 8][ks + lc + 4];
            }
            #pragma unroll
            for (int ni = 0; ni < 4; ni++) {
                int n = wn + ni * 8;
                b[ni][0] = Bs[s][ks + lc    ][n + lr];
                b[ni][1] = Bs[s][ks + lc + 4][n + lr];
            }
            #pragma unroll
            for (int mi = 0; mi < 4; mi++)
                #pragma unroll
                for (int ni = 0; ni < 4; ni++)
                    MMA_TF32(acc[mi][ni], a[mi], b[ni][0], b[ni][1]);
        }

        if (nxt) sts(s ^ 1);
        __syncthreads();
        s ^= 1;
    }

    const float* bias = gb.bias;
    float* C = gb.C;
    #pragma unroll
    for (int mi = 0; mi < 4; mi++) {
        #pragma unroll
        for (int ni = 0; ni < 4; ni++) {
            int r = row0 + wm + mi * 16 + lr;
            int c = col0 + wn + ni * 8 + lc * 2;
            float b0 = bias[c], b1 = bias[c + 1];
            *reinterpret_cast<float2*>(&C[(size_t)r * N + c]) =
                make_float2(acc[mi][ni][0] + b0, acc[mi][ni][1] + b1);
            *reinterpret_cast<float2*>(&C[(size_t)(r + 8) * N + c]) =
                make_float2(acc[mi][ni][2] + b0, acc[mi][ni][3] + b1);
        }
    }
}

// ---------------------------------------------------------------------------
// TF32 tensor-core flash attention. Block = (qtile 64, head, z=attn*8+batch).
// 128 threads / 4 warps; warp owns 16 q-rows. Q A-frags register-resident.
// K/V share one smem buffer; P routed via smem for the PV mma.
// ---------------------------------------------------------------------------
struct AttnArgs { const float* Q; const float* K; const float* V; float* O; };
struct AttnBatch { AttnArgs a[4]; };

__global__ __launch_bounds__(128) void attn_tc(AttnBatch batch)
{
    __shared__ uint32_t KVs[64][68];
    __shared__ uint32_t Ps[64][68];

    const int tid  = threadIdx.x;
    const int lane = tid & 31;
    const int warp = tid >> 5;
    const int lr = lane >> 2;     // 0..7
    const int lc = lane & 3;      // 0..3
    const int m0 = warp * 16;

    const int qt = blockIdx.x;
    const int h  = blockIdx.y;
    const int b  = blockIdx.z & 7;
    const AttnArgs A = batch.a[blockIdx.z >> 3];

    const float* Qb = A.Q + ((size_t)b * SEQ + qt * 64) * DIM + h * DHEAD;
    const float* Kb = A.K + (size_t)b * SEQ * DIM + h * DHEAD;
    const float* Vb = A.V + (size_t)b * SEQ * DIM + h * DHEAD;

    // Stage Q tile (tf32) into KVs, pull per-warp A-frags into regs.
    #pragma unroll
    for (int i = 0; i < 8; i++) {
        int idx = tid + i * 128;
        int r = idx >> 4, c4 = (idx & 15) * 4;
        float4 v = *reinterpret_cast<const float4*>(&Qb[(size_t)r * DIM + c4]);
        KVs[r][c4+0] = f2tf32(v.x); KVs[r][c4+1] = f2tf32(v.y);
        KVs[r][c4+2] = f2tf32(v.z); KVs[r][c4+3] = f2tf32(v.w);
    }
    __syncthreads();
    uint32_t qa[8][4];
    #pragma unroll
    for (int kk = 0; kk < 8; kk++) {
        qa[kk][0] = KVs[m0 + lr    ][kk*8 + lc    ];
        qa[kk][1] = KVs[m0 + lr + 8][kk*8 + lc    ];
        qa[kk][2] = KVs[m0 + lr    ][kk*8 + lc + 4];
        qa[kk][3] = KVs[m0 + lr + 8][kk*8 + lc + 4];
    }
    __syncthreads();

    float o[8][4] = {};
    float mrow0 = -1e30f, mrow1 = -1e30f, lrow0 = 0.f, lrow1 = 0.f;
    const float Cs = 0.1803368801f;  // 0.125 * log2(e)

    for (int kt = 0; kt < 8; kt++) {
        // K tile -> KVs [kcol][d]
        #pragma unroll
        for (int i = 0; i < 8; i++) {
            int idx = tid + i * 128;
            int r = idx >> 4, c4 = (idx & 15) * 4;
            float4 v = *reinterpret_cast<const float4*>(&Kb[(size_t)(kt*64 + r) * DIM + c4]);
            KVs[r][c4+0] = f2tf32(v.x); KVs[r][c4+1] = f2tf32(v.y);
            KVs[r][c4+2] = f2tf32(v.z); KVs[r][c4+3] = f2tf32(v.w);
        }
        __syncthreads();

        // S = Q @ K^T  (warp: 16 x 64)
        float sc[8][4] = {};
        #pragma unroll
        for (int kk = 0; kk < 8; kk++) {
            #pragma unroll
            for (int ni = 0; ni < 8; ni++) {
                uint32_t b0 = KVs[ni*8 + lr][kk*8 + lc    ];
                uint32_t b1 = KVs[ni*8 + lr][kk*8 + lc + 4];
                MMA_TF32(sc[ni], qa[kk], b0, b1);
            }
        }
        __syncthreads();   // all warps done reading K from KVs

        // Online softmax (rows lr -> c0/c1, lr+8 -> c2/c3)
        float rm0 = -1e30f, rm1 = -1e30f;
        #pragma unroll
        for (int ni = 0; ni < 8; ni++) {
            rm0 = fmaxf(rm0, fmaxf(sc[ni][0], sc[ni][1]));
            rm1 = fmaxf(rm1, fmaxf(sc[ni][2], sc[ni][3]));
        }
        rm0 = fmaxf(rm0, __shfl_xor_sync(0xffffffffu, rm0, 1));
        rm0 = fmaxf(rm0, __shfl_xor_sync(0xffffffffu, rm0, 2));
        rm1 = fmaxf(rm1, __shfl_xor_sync(0xffffffffu, rm1, 1));
        rm1 = fmaxf(rm1, __shfl_xor_sync(0xffffffffu, rm1, 2));

        float nm0 = fmaxf(mrow0, rm0), nm1 = fmaxf(mrow1, rm1);
        float corr0 = exp2f((mrow0 - nm0) * Cs);
        float corr1 = exp2f((mrow1 - nm1) * Cs);
        mrow0 = nm0; mrow1 = nm1;

        float s0 = 0.f, s1 = 0.f;
        #pragma unroll
        for (int ni = 0; ni < 8; ni++) {
            float e0 = exp2f((sc[ni][0] - nm0) * Cs);
            float e1 = exp2f((sc[ni][1] - nm0) * Cs);
            float e2 = exp2f((sc[ni][2] - nm1) * Cs);
            float e3 = exp2f((sc[ni][3] - nm1) * Cs);
            s0 += e0 + e1; s1 += e2 + e3;
            Ps[m0 + lr    ][ni*8 + 2*lc    ] = f2tf32(e0);
            Ps[m0 + lr    ][ni*8 + 2*lc + 1] = f2tf32(e1);
            Ps[m0 + lr + 8][ni*8 + 2*lc    ] = f2tf32(e2);
            Ps[m0 + lr + 8][ni*8 + 2*lc + 1] = f2tf32(e3);
        }
        s0 += __shfl_xor_sync(0xffffffffu, s0, 1);
        s0 += __shfl_xor_sync(0xffffffffu, s0, 2);
        s1 += __shfl_xor_sync(0xffffffffu, s1, 1);
        s1 += __shfl_xor_sync(0xffffffffu, s1, 2);
        lrow0 = lrow0 * corr0 + s0;
        lrow1 = lrow1 * corr1 + s1;
        #pragma unroll
        for (int ni = 0; ni < 8; ni++) {
            o[ni][0] *= corr0; o[ni][1] *= corr0;
            o[ni][2] *= corr1; o[ni][3] *= corr1;
        }
        __syncwarp();

        // V tile -> KVs [krow][d]
        #pragma unroll
        for (int i = 0; i < 8; i++) {
            int idx = tid + i * 128;
            int r = idx >> 4, c4 = (idx & 15) * 4;
            float4 v = *reinterpret_cast<const float4*>(&Vb[(size_t)(kt*64 + r) * DIM + c4]);
            KVs[r][c4+0] = f2tf32(v.x); KVs[r][c4+1] = f2tf32(v.y);
            KVs[r][c4+2] = f2tf32(v.z); KVs[r][c4+3] = f2tf32(v.w);
        }
        __syncthreads();

        // O += P @ V  (warp reads only its own P rows)
        #pragma unroll
        for (int kk = 0; kk < 8; kk++) {
            uint32_t pa[4];
            pa[0] = Ps[m0 + lr    ][kk*8 + lc    ];
            pa[1] = Ps[m0 + lr + 8][kk*8 + lc    ];
            pa[2] = Ps[m0 + lr    ][kk*8 + lc + 4];
            pa[3] = Ps[m0 + lr + 8][kk*8 + lc + 4];
            #pragma unroll
            for (int ni = 0; ni < 8; ni++) {
                uint32_t b0 = KVs[kk*8 + lc    ][ni*8 + lr];
                uint32_t b1 = KVs[kk*8 + lc + 4][ni*8 + lr];
                MMA_TF32(o[ni], pa, b0, b1);
            }
        }
        __syncthreads();   // before next K overwrite
    }

    // Epilogue
    float inv0 = 1.f / lrow0, inv1 = 1.f / lrow1;
    #pragma unroll
    for (int ni = 0; ni < 8; ni++) {
        size_t base = ((size_t)b * SEQ + qt*64 + m0 + lr) * DIM + h * DHEAD + ni*8 + 2*lc;
        *reinterpret_cast<float2*>(&A.O[base]) =
            make_float2(o[ni][0] * inv0, o[ni][1] * inv0);
        *reinterpret_cast<float2*>(&A.O[base + 8 * DIM]) =
            make_float2(o[ni][2] * inv1, o[ni][3] * inv1);
    }
}

// ---------------------------------------------------------------------------
// Host launcher: 4 launches total.
// ---------------------------------------------------------------------------
extern "C" void kernel_launch(void* const* d_in, const int* in_sizes, int n_in,
                              void* d_out, int out_size)
{
    const float* hs   = (const float*)d_in[0];
    const float* mol  = (const float*)d_in[1];
    const float* Wq   = (const float*)d_in[2];  const float* bq   = (const float*)d_in[3];
    const float* Wk   = (const float*)d_in[4];  const float* bk   = (const float*)d_in[5];
    const float* Wv   = (const float*)d_in[6];  const float* bv   = (const float*)d_in[7];
    const float* Wqm  = (const float*)d_in[8];  const float* bqm  = (const float*)d_in[9];
    const float* Wkm  = (const float*)d_in[10]; const float* bkm  = (const float*)d_in[11];
    const float* Wvm  = (const float*)d_in[12]; const float* bvm  = (const float*)d_in[13];
    const float* Wfc  = (const float*)d_in[14]; const float* bfc  = (const float*)d_in[15];
    const float* Wfcm = (const float*)d_in[16]; const float* bfcm = (const float*)d_in[17];
    const float* Wo   = (const float*)d_in[18]; const float* bo   = (const float*)d_in[19];
    const float* Wom  = (const float*)d_in[20]; const float* bom  = (const float*)d_in[21];

    float* outp = (float*)d_out;
    float* outm = outp + (size_t)MAT;

    float* base = nullptr;
    cudaGetSymbolAddress((void**)&base, g_scratch);
    float* q   = base + 0ULL  * MAT;
    float* k   = base + 1ULL  * MAT;
    float* v   = base + 2ULL  * MAT;
    float* qm  = base + 3ULL  * MAT;
    float* km  = base + 4ULL  * MAT;
    float* vm  = base + 5ULL  * MAT;
    float* app = base + 6ULL  * MAT;
    float* amp = base + 7ULL  * MAT;
    float* amm = base + 8ULL  * MAT;
    float* apm = base + 9ULL  * MAT;
    float* c1  = base + 10ULL * MAT;
    float* c2  = base + 11ULL * MAT;

    // 1) Six projections in ONE launch
    GBatch proj = {{
        { hs,  nullptr, Wq,  bq,  q,  DIM, 0 },
        { hs,  nullptr, Wk,  bk,  k,  DIM, 0 },
        { hs,  nullptr, Wv,  bv,  v,  DIM, 0 },
        { mol, nullptr, Wqm, bqm, qm, DIM, 0 },
        { mol, nullptr, Wkm, bkm, km, DIM, 0 },
        { mol, nullptr, Wvm, bvm, vm, DIM, 0 },
    }};
    gemm_tf32<<<dim3(DIM/128, ROWS/128, 6), 256>>>(proj);

    // 2) Four attentions in ONE launch (tensor cores)
    AttnBatch ab = {{
        { q,  k,  v,  app },
        { qm, k,  v,  amp },
        { qm, km, vm, amm },
        { q,  km, vm, apm },
    }};
    attn_tc<<<dim3(SEQ/64, HEADS, 4*BATCH), 128>>>(ab);

    // 3) Concat-FC pair (dual-A, K=1536)
    GBatch fc = {{
        { app, amp, Wfc,  bfc,  c1, DIM, DIM },
        { amm, apm, Wfcm, bfcm, c2, DIM, DIM },
        {}, {}, {}, {},
    }};
    gemm_tf32<<<dim3(DIM/128, ROWS/128, 2), 256>>>(fc);

    // 4) Output projection pair
    GBatch outg = {{
        { c1, nullptr, Wo,  bo,  outp, DIM, 0 },
        { c2, nullptr, Wom, bom, outm, DIM, 0 },
        {}, {}, {}, {},
    }};
    gemm_tf32<<<dim3(DIM/128, ROWS/128, 2), 256>>>(outg);
}

// round 4
// speedup vs baseline: 3.6973x; 1.2915x over previous
#include <cuda_runtime.h>
#include <cuda_bf16.h>
#include <cstdint>

#define BATCH 8
#define SEQ   512
#define DIM   768
#define HEADS 12
#define DHEAD 64
#define ROWS  (BATCH * SEQ)        // 4096
#define MAT   (ROWS * DIM)         // 3145728

__device__ float g_scratch[12ULL * MAT];

__device__ __forceinline__ uint32_t f2tf32(float x) {
    uint32_t u;
    asm("cvt.rna.tf32.f32 %0, %1;" : "=r"(u) : "f"(x));
    return u;
}

#define MMA_TF32(D, A, B0, B1)                                              \
    asm volatile(                                                           \
        "mma.sync.aligned.m16n8k8.row.col.f32.tf32.tf32.f32 "               \
        "{%0,%1,%2,%3}, {%4,%5,%6,%7}, {%8,%9}, {%0,%1,%2,%3};"             \
        : "+f"((D)[0]), "+f"((D)[1]), "+f"((D)[2]), "+f"((D)[3])            \
        : "r"((A)[0]), "r"((A)[1]), "r"((A)[2]), "r"((A)[3]),               \
          "r"(B0), "r"(B1))

__device__ __forceinline__ void cp_async16(void* smem_ptr, const void* gptr) {
    uint32_t saddr = (uint32_t)__cvta_generic_to_shared(smem_ptr);
    asm volatile("cp.async.ca.shared.global [%0], [%1], 16;" :: "r"(saddr), "l"(gptr));
}

// ---------------------------------------------------------------------------
// Batched TF32 GEMM (unchanged from R3, plus optional tf32-rounded output):
//   C = A1[M,K1] @ W[0:K1,:] + A2[M,K2] @ W[K1:,:] + bias
// ---------------------------------------------------------------------------
struct GB { const float* A1; const float* A2; const float* W; const float* bias;
            float* C; int K1; int K2; int round_out; };
struct GBatch { GB g[6]; };

__global__ __launch_bounds__(256, 2) void gemm_tf32(GBatch batch)
{
    __shared__ uint32_t As[2][128][20];
    __shared__ uint32_t Bs[2][16][136];

    const GB gb = batch.g[blockIdx.z];
    const float* __restrict__ A1 = gb.A1;
    const float* __restrict__ A2 = gb.A2;
    const float* __restrict__ W  = gb.W;
    const int K1 = gb.K1, K2 = gb.K2;
    const int N = DIM;

    const int tid  = threadIdx.x;
    const int lane = tid & 31;
    const int warp = tid >> 5;
    const int wm = (warp >> 2) * 64;
    const int wn = (warp & 3) * 32;
    const int row0 = blockIdx.y * 128;
    const int col0 = blockIdx.x * 128;
    const int Ktot = K1 + K2;

    float acc[4][4][4] = {};
    float4 ra[2], rb[2];

    auto ldg = [&](int kt) {
        const float* A; int kc, lda;
        if (kt < K1) { A = A1; kc = kt;      lda = K1; }
        else         { A = A2; kc = kt - K1; lda = K2; }
        #pragma unroll
        for (int lo = 0; lo < 2; lo++) {
            int idx = tid + lo * 256;
            int r = idx >> 2, c4 = (idx & 3) * 4;
            ra[lo] = *reinterpret_cast<const float4*>(&A[(size_t)(row0 + r) * lda + kc + c4]);
        }
        #pragma unroll
        for (int lo = 0; lo < 2; lo++) {
            int idx = tid + lo * 256;
            int r = idx >> 5, c4 = (idx & 31) * 4;
            rb[lo] = *reinterpret_cast<const float4*>(&W[(size_t)(kt + r) * N + col0 + c4]);
        }
    };
    auto sts = [&](int s) {
        #pragma unroll
        for (int lo = 0; lo < 2; lo++) {
            int idx = tid + lo * 256;
            int r = idx >> 2, c4 = (idx & 3) * 4;
            uint4 u = make_uint4(f2tf32(ra[lo].x), f2tf32(ra[lo].y),
                                 f2tf32(ra[lo].z), f2tf32(ra[lo].w));
            *reinterpret_cast<uint4*>(&As[s][r][c4]) = u;
        }
        #pragma unroll
        for (int lo = 0; lo < 2; lo++) {
            int idx = tid + lo * 256;
            int r = idx >> 5, c4 = (idx & 31) * 4;
            uint4 u = make_uint4(f2tf32(rb[lo].x), f2tf32(rb[lo].y),
                                 f2tf32(rb[lo].z), f2tf32(rb[lo].w));
            *reinterpret_cast<uint4*>(&Bs[s][r][c4]) = u;
        }
    };

    ldg(0); sts(0);
    __syncthreads();

    const int lr = lane >> 2;
    const int lc = lane & 3;
    int s = 0;
    for (int kt = 0; kt < Ktot; kt += 16) {
        const bool nxt = (kt + 16) < Ktot;
        if (nxt) ldg(kt + 16);

        #pragma unroll
        for (int ks = 0; ks < 16; ks += 8) {
            uint32_t a[4][4], b[4][2];
            #pragma unroll
            for (int mi = 0; mi < 4; mi++) {
                int m = wm + mi * 16;
                a[mi][0] = As[s][m + lr    ][ks + lc    ];
                a[mi][1] = As[s][m + lr + 8][ks + lc    ];
                a[mi][2] = As[s][m + lr    ][ks + lc + 4];
                a[mi][3] = As[s][m + lr + 8][ks + lc + 4];
            }
            #pragma unroll
            for (int ni = 0; ni < 4; ni++) {
                int n = wn + ni * 8;
                b[ni][0] = Bs[s][ks + lc    ][n + lr];
                b[ni][1] = Bs[s][ks + lc + 4][n + lr];
            }
            #pragma unroll
            for (int mi = 0; mi < 4; mi++)
                #pragma unroll
                for (int ni = 0; ni < 4; ni++)
                    MMA_TF32(acc[mi][ni], a[mi], b[ni][0], b[ni][1]);
        }

        if (nxt) sts(s ^ 1);
        __syncthreads();
        s ^= 1;
    }

    const float* bias = gb.bias;
    float* C = gb.C;
    const bool ro = gb.round_out != 0;
    #pragma unroll
    for (int mi = 0; mi < 4; mi++) {
        #pragma unroll
        for (int ni = 0; ni < 4; ni++) {
            int r = row0 + wm + mi * 16 + lr;
            int c = col0 + wn + ni * 8 + lc * 2;
            float b0 = bias[c], b1 = bias[c + 1];
            float v0 = acc[mi][ni][0] + b0, v1 = acc[mi][ni][1] + b1;
            float v2 = acc[mi][ni][2] + b0, v3 = acc[mi][ni][3] + b1;
            if (ro) {
                v0 = __uint_as_float(f2tf32(v0)); v1 = __uint_as_float(f2tf32(v1));
                v2 = __uint_as_float(f2tf32(v2)); v3 = __uint_as_float(f2tf32(v3));
            }
            *reinterpret_cast<float2*>(&C[(size_t)r * N + c]) = make_float2(v0, v1);
            *reinterpret_cast<float2*>(&C[(size_t)(r + 8) * N + c]) = make_float2(v2, v3);
        }
    }
}

// ---------------------------------------------------------------------------
// Merged dual-attention, TF32 tensor cores, cp.async double-buffered K/V.
// Block = 256 thr / 8 warps. Warps 0-3: Q1 set; warps 4-7: Q2 set (same K/V).
// Inputs pre-rounded to tf32 -> raw copies, no cvt on K/V/Q paths.
// Dynamic smem: Kb[2] Vb[2] Ps[2] of 64x68 words = 104448 B.
// ---------------------------------------------------------------------------
struct AttnJob { const float* Q1; const float* Q2; const float* K; const float* V;
                 float* O1; float* O2; };
struct AttnBatch2 { AttnJob j[2]; };

extern __shared__ uint32_t dsm[];

__global__ __launch_bounds__(256) void attn_tc(AttnBatch2 batch)
{
    typedef uint32_t Tile[64][68];
    Tile* Kb = (Tile*)dsm;                  // [2]
    Tile* Vb = (Tile*)(dsm + 2 * 64 * 68);  // [2]
    Tile* Ps = (Tile*)(dsm + 4 * 64 * 68);  // [2] (also Q staging)

    const int tid  = threadIdx.x;
    const int lane = tid & 31;
    const int warp = tid >> 5;
    const int qset = warp >> 2;
    const int wm   = (warp & 3) * 16;
    const int lr = lane >> 2, lc = lane & 3;

    const int qt = blockIdx.x;
    const int h  = blockIdx.y;
    const int b  = blockIdx.z & 7;
    const AttnJob J = batch.j[blockIdx.z >> 3];

    const float* Qg = (qset == 0 ? J.Q1 : J.Q2) + ((size_t)b * SEQ + qt * 64) * DIM + h * DHEAD;
    const float* Kg = J.K + (size_t)b * SEQ * DIM + h * DHEAD;
    const float* Vg = J.V + (size_t)b * SEQ * DIM + h * DHEAD;
    float* Og = (qset == 0 ? J.O1 : J.O2);

    auto issue_kv = [&](int kt, int buf) {
        #pragma unroll
        for (int i = 0; i < 4; i++) {
            int idx = tid + i * 256;
            int r = idx >> 4, c4 = (idx & 15) * 4;
            const size_t go = (size_t)(kt * 64 + r) * DIM + c4;
            cp_async16(&Kb[buf][r][c4], &Kg[go]);
            cp_async16(&Vb[buf][r][c4], &Vg[go]);
        }
    };

    // Prologue: pipeline K/V tiles 0 and 1.
    issue_kv(0, 0);
    asm volatile("cp.async.commit_group;");
    issue_kv(1, 1);
    asm volatile("cp.async.commit_group;");

    // Stage Q (raw tf32 bits) into Ps[qset], then pull per-warp A-frags.
    {
        int t = tid & 127;
        #pragma unroll
        for (int i = 0; i < 4; i++) {
            int idx = t + i * 128;
            int r = idx >> 3, c4 = (idx & 7) * 8;   // 8 floats per thread-chunk
            float4 v0 = *reinterpret_cast<const float4*>(&Qg[(size_t)r * DIM + c4]);
            float4 v1 = *reinterpret_cast<const float4*>(&Qg[(size_t)r * DIM + c4 + 4]);
            *reinterpret_cast<float4*>(&Ps[qset][r][c4])     = v0;
            *reinterpret_cast<float4*>(&Ps[qset][r][c4 + 4]) = v1;
        }
    }
    __syncthreads();

    uint32_t qa[8][4];
    #pragma unroll
    for (int kk = 0; kk < 8; kk++) {
        qa[kk][0] = Ps[qset][wm + lr    ][kk * 8 + lc    ];
        qa[kk][1] = Ps[qset][wm + lr + 8][kk * 8 + lc    ];
        qa[kk][2] = Ps[qset][wm + lr    ][kk * 8 + lc + 4];
        qa[kk][3] = Ps[qset][wm + lr + 8][kk * 8 + lc + 4];
    }
    // No extra sync needed: each warp later writes only its own Ps rows.

    float o[8][4] = {};
    float mrow0 = -1e30f, mrow1 = -1e30f, lrow0 = 0.f, lrow1 = 0.f;
    const float Cs = 0.1803368801f;  // 0.125 * log2(e)

    for (int kt = 0; kt < 8; kt++) {
        const int buf = kt & 1;
        asm volatile("cp.async.wait_group 1;" ::: "memory");
        __syncthreads();

        // S = Q @ K^T
        float sc[8][4] = {};
        #pragma unroll
        for (int kk = 0; kk < 8; kk++)
            #pragma unroll
            for (int ni = 0; ni < 8; ni++) {
                uint32_t b0 = Kb[buf][ni * 8 + lr][kk * 8 + lc    ];
                uint32_t b1 = Kb[buf][ni * 8 + lr][kk * 8 + lc + 4];
                MMA_TF32(sc[ni], qa[kk], b0, b1);
            }

        // Online softmax
        float rm0 = -1e30f, rm1 = -1e30f;
        #pragma unroll
        for (int ni = 0; ni < 8; ni++) {
            rm0 = fmaxf(rm0, fmaxf(sc[ni][0], sc[ni][1]));
            rm1 = fmaxf(rm1, fmaxf(sc[ni][2], sc[ni][3]));
        }
        rm0 = fmaxf(rm0, __shfl_xor_sync(0xffffffffu, rm0, 1));
        rm0 = fmaxf(rm0, __shfl_xor_sync(0xffffffffu, rm0, 2));
        rm1 = fmaxf(rm1, __shfl_xor_sync(0xffffffffu, rm1, 1));
        rm1 = fmaxf(rm1, __shfl_xor_sync(0xffffffffu, rm1, 2));

        float nm0 = fmaxf(mrow0, rm0), nm1 = fmaxf(mrow1, rm1);
        float corr0 = exp2f((mrow0 - nm0) * Cs);
        float corr1 = exp2f((mrow1 - nm1) * Cs);
        mrow0 = nm0; mrow1 = nm1;

        float s0 = 0.f, s1 = 0.f;
        #pragma unroll
        for (int ni = 0; ni < 8; ni++) {
            float e0 = exp2f((sc[ni][0] - nm0) * Cs);
            float e1 = exp2f((sc[ni][1] - nm0) * Cs);
            float e2 = exp2f((sc[ni][2] - nm1) * Cs);
            float e3 = exp2f((sc[ni][3] - nm1) * Cs);
            s0 += e0 + e1; s1 += e2 + e3;
            uint64_t p01 = (uint64_t)f2tf32(e0) | ((uint64_t)f2tf32(e1) << 32);
            uint64_t p23 = (uint64_t)f2tf32(e2) | ((uint64_t)f2tf32(e3) << 32);
            *reinterpret_cast<uint64_t*>(&Ps[qset][wm + lr    ][ni * 8 + 2 * lc]) = p01;
            *reinterpret_cast<uint64_t*>(&Ps[qset][wm + lr + 8][ni * 8 + 2 * lc]) = p23;
        }
        s0 += __shfl_xor_sync(0xffffffffu, s0, 1);
        s0 += __shfl_xor_sync(0xffffffffu, s0, 2);
        s1 += __shfl_xor_sync(0xffffffffu, s1, 1);
        s1 += __shfl_xor_sync(0xffffffffu, s1, 2);
        lrow0 = lrow0 * corr0 + s0;
        lrow1 = lrow1 * corr1 + s1;
        #pragma unroll
        for (int ni = 0; ni < 8; ni++) {
            o[ni][0] *= corr0; o[ni][1] *= corr0;
            o[ni][2] *= corr1; o[ni][3] *= corr1;
        }
        __syncwarp();

        // O += P @ V
        #pragma unroll
        for (int kk = 0; kk < 8; kk++) {
            uint32_t pa[4];
            pa[0] = Ps[qset][wm + lr    ][kk * 8 + lc    ];
            pa[1] = Ps[qset][wm + lr + 8][kk * 8 + lc    ];
            pa[2] = Ps[qset][wm + lr    ][kk * 8 + lc + 4];
            pa[3] = Ps[qset][wm + lr + 8][kk * 8 + lc + 4];
            #pragma unroll
            for (int ni = 0; ni < 8; ni++) {
                uint32_t b0 = Vb[buf][kk * 8 + lc    ][ni * 8 + lr];
                uint32_t b1 = Vb[buf][kk * 8 + lc + 4][ni * 8 + lr];
                MMA_TF32(o[ni], pa, b0, b1);
            }
        }
        __syncthreads();   // everyone done with buf before overwrite

        if (kt + 2 < 8) issue_kv(kt + 2, buf);
        asm volatile("cp.async.commit_group;");
    }

    // Epilogue
    float inv0 = 1.f / lrow0, inv1 = 1.f / lrow1;
    #pragma unroll
    for (int ni = 0; ni < 8; ni++) {
        size_t base = ((size_t)b * SEQ + qt * 64 + wm + lr) * DIM + h * DHEAD + ni * 8 + 2 * lc;
        *reinterpret_cast<float2*>(&Og[base]) =
            make_float2(o[ni][0] * inv0, o[ni][1] * inv0);
        *reinterpret_cast<float2*>(&Og[base + 8 * DIM]) =
            make_float2(o[ni][2] * inv1, o[ni][3] * inv1);
    }
}

// ---------------------------------------------------------------------------
// Host launcher: 4 launches.
// ---------------------------------------------------------------------------
extern "C" void kernel_launch(void* const* d_in, const int* in_sizes, int n_in,
                              void* d_out, int out_size)
{
    const float* hs   = (const float*)d_in[0];
    const float* mol  = (const float*)d_in[1];
    const float* Wq   = (const float*)d_in[2];  const float* bq   = (const float*)d_in[3];
    const float* Wk   = (const float*)d_in[4];  const float* bk   = (const float*)d_in[5];
    const float* Wv   = (const float*)d_in[6];  const float* bv   = (const float*)d_in[7];
    const float* Wqm  = (const float*)d_in[8];  const float* bqm  = (const float*)d_in[9];
    const float* Wkm  = (const float*)d_in[10]; const float* bkm  = (const float*)d_in[11];
    const float* Wvm  = (const float*)d_in[12]; const float* bvm  = (const float*)d_in[13];
    const float* Wfc  = (const float*)d_in[14]; const float* bfc  = (const float*)d_in[15];
    const float* Wfcm = (const float*)d_in[16]; const float* bfcm = (const float*)d_in[17];
    const float* Wo   = (const float*)d_in[18]; const float* bo   = (const float*)d_in[19];
    const float* Wom  = (const float*)d_in[20]; const float* bom  = (const float*)d_in[21];

    float* outp = (float*)d_out;
    float* outm = outp + (size_t)MAT;

    float* base = nullptr;
    cudaGetSymbolAddress((void**)&base, g_scratch);
    float* q   = base + 0ULL  * MAT;
    float* k   = base + 1ULL  * MAT;
    float* v   = base + 2ULL  * MAT;
    float* qm  = base + 3ULL  * MAT;
    float* km  = base + 4ULL  * MAT;
    float* vm  = base + 5ULL  * MAT;
    float* app = base + 6ULL  * MAT;
    float* amp = base + 7ULL  * MAT;
    float* amm = base + 8ULL  * MAT;
    float* apm = base + 9ULL  * MAT;
    float* c1  = base + 10ULL * MAT;
    float* c2  = base + 11ULL * MAT;

    // 1) Six projections, ONE launch; outputs rounded to tf32 for attention.
    GBatch proj = {{
        { hs,  nullptr, Wq,  bq,  q,  DIM, 0, 1 },
        { hs,  nullptr, Wk,  bk,  k,  DIM, 0, 1 },
        { hs,  nullptr, Wv,  bv,  v,  DIM, 0, 1 },
        { mol, nullptr, Wqm, bqm, qm, DIM, 0, 1 },
        { mol, nullptr, Wkm, bkm, km, DIM, 0, 1 },
        { mol, nullptr, Wvm, bvm, vm, DIM, 0, 1 },
    }};
    gemm_tf32<<<dim3(DIM/128, ROWS/128, 6), 256>>>(proj);

    // 2) Merged dual attention, ONE launch.
    const int ATTN_SMEM = 6 * 64 * 68 * 4;   // 104448 B
    cudaFuncSetAttribute(attn_tc, cudaFuncAttributeMaxDynamicSharedMemorySize, ATTN_SMEM);
    AttnBatch2 ab = {{
        { q,  qm, k,  v,  app, amp },   // prot KV group
        { qm, q,  km, vm, amm, apm },   // mol  KV group
    }};
    attn_tc<<<dim3(SEQ/64, HEADS, 2*BATCH), 256, ATTN_SMEM>>>(ab);

    // 3) Concat-FC pair (dual-A, K=1536)
    GBatch fc = {{
        { app, amp, Wfc,  bfc,  c1, DIM, DIM, 0 },
        { amm, apm, Wfcm, bfcm, c2, DIM, DIM, 0 },
        {}, {}, {}, {},
    }};
    gemm_tf32<<<dim3(DIM/128, ROWS/128, 2), 256>>>(fc);

    // 4) Output projection pair
    GBatch outg = {{
        { c1, nullptr, Wo,  bo,  outp, DIM, 0, 0 },
        { c2, nullptr, Wom, bom, outm, DIM, 0, 0 },
        {}, {}, {}, {},
    }};
    gemm_tf32<<<dim3(DIM/128, ROWS/128, 2), 256>>>(outg);
}

// round 6
// speedup vs baseline: 7.1819x; 1.9425x over previous
#include <cuda_runtime.h>
#include <cuda_fp16.h>
#include <cstdint>

#define BATCH 8
#define SEQ   512
#define DIM   768
#define HEADS 12
#define DHEAD 64
#define ROWS  (BATCH * SEQ)        // 4096
#define MAT   (ROWS * DIM)         // 3145728
#define W768  (768 * 768)
#define W1536 (1536 * 768)

__device__ float g_scratch[17ULL * MAT];

__device__ __forceinline__ uint32_t packf16(float lo, float hi) {
    uint32_t r;
    asm("cvt.rn.f16x2.f32 %0, %1, %2;" : "=r"(r) : "f"(hi), "f"(lo));
    return r;
}

#define MMA_F16(D, A, B0, B1)                                               \
    asm volatile(                                                           \
        "mma.sync.aligned.m16n8k16.row.col.f32.f16.f16.f32 "                \
        "{%0,%1,%2,%3}, {%4,%5,%6,%7}, {%8,%9}, {%0,%1,%2,%3};"             \
        : "+f"((D)[0]), "+f"((D)[1]), "+f"((D)[2]), "+f"((D)[3])            \
        : "r"((A)[0]), "r"((A)[1]), "r"((A)[2]), "r"((A)[3]),               \
          "r"(B0), "r"(B1))

__device__ __forceinline__ void cp16(void* smem_ptr, const void* gptr) {
    uint32_t saddr = (uint32_t)__cvta_generic_to_shared(smem_ptr);
    asm volatile("cp.async.ca.shared.global [%0], [%1], 16;" :: "r"(saddr), "l"(gptr));
}

// ---------------------------------------------------------------------------
// Pre-pass 1: transpose weights to [N,K] fp16: dst[n*K+k] = h(src[k*N+n])
// ---------------------------------------------------------------------------
struct TJ { const float* src; __half* dst; int K; int N; };
struct TBatch { TJ j[10]; };

__global__ __launch_bounds__(256) void transpose_round(TBatch tb)
{
    __shared__ float t[32][33];
    const TJ J = tb.j[blockIdx.z];
    int k0 = blockIdx.x * 32, n0 = blockIdx.y * 32;
    if (k0 >= J.K || n0 >= J.N) return;
    int tx = threadIdx.x & 31, ty = threadIdx.x >> 5;   // 32 x 8
    #pragma unroll
    for (int i = 0; i < 4; i++)
        t[ty + i * 8][tx] = J.src[(size_t)(k0 + ty + i * 8) * J.N + n0 + tx];
    __syncthreads();
    #pragma unroll
    for (int i = 0; i < 4; i++)
        J.dst[(size_t)(n0 + ty + i * 8) * J.K + k0 + tx] =
            __float2half(t[tx][ty + i * 8]);
}

// Pre-pass 2: fp32 -> fp16 copies of hs, mol
__global__ __launch_bounds__(256) void round_copy(const float* __restrict__ a,
                                                  __half* __restrict__ oa,
                                                  const float* __restrict__ b,
                                                  __half* __restrict__ ob)
{
    size_t i = (size_t)blockIdx.x * 256 + threadIdx.x;
    const float* s = blockIdx.y ? b : a;
    __half* d = blockIdx.y ? ob : oa;
    float4 v = *reinterpret_cast<const float4*>(&s[i * 4]);
    uint2 u = make_uint2(packf16(v.x, v.y), packf16(v.z, v.w));
    *reinterpret_cast<uint2*>(&d[i * 4]) = u;
}

// Pre-pass 3: transpose v, vm (fp16 [b][s][768]) -> vT [b][768][512]
__global__ __launch_bounds__(256) void transpose_v(
    const __half* __restrict__ v, __half* __restrict__ vt,
    const __half* __restrict__ vm, __half* __restrict__ vmt)
{
    __shared__ __half t[64][72];
    const int dt = blockIdx.x * 64, st = blockIdx.y * 64;
    const int b = blockIdx.z & 7;
    const __half* src = (blockIdx.z >> 3) ? vm : v;
    __half* dst = (blockIdx.z >> 3) ? vmt : vt;
    const int tid = threadIdx.x;
    #pragma unroll
    for (int i = 0; i < 8; i++) {
        int idx = tid + i * 256;
        int r = idx >> 5, w = idx & 31;
        *reinterpret_cast<uint32_t*>(&t[r][w * 2]) =
            *reinterpret_cast<const uint32_t*>(&src[((size_t)(b * SEQ + st + r)) * DIM + dt + w * 2]);
    }
    __syncthreads();
    #pragma unroll
    for (int i = 0; i < 8; i++) {
        int idx = tid + i * 256;
        int r = idx >> 5, w = idx & 31;   // r = d-local, w = s-pair
        __half2 p = __halves2half2(t[w * 2][r], t[w * 2 + 1][r]);
        *reinterpret_cast<__half2*>(&dst[((size_t)(b * DIM + dt + r)) * SEQ + st + w * 2]) = p;
    }
}

// ---------------------------------------------------------------------------
// fp16 GEMM (mma.sync m16n8k16): C = A1|A2 @ Wt^T + bias.
// A [M,K] fp16 row-major; Wt [N,K] fp16. Block 128x128, BK=32, 8 warps 2x4.
// As/Bs stride 20 words (conflict-free: (20*lr+lc)%32 distinct).
// ---------------------------------------------------------------------------
struct GB { const __half* A1; const __half* A2; const __half* Wt; const float* bias;
            void* C; int K1; int K2; int half_out; };
struct GBatch { GB g[6]; };

__global__ __launch_bounds__(256) void gemm_f16(GBatch batch)
{
    __shared__ uint32_t As[2][128][20];   // 16 data words + 4 pad
    __shared__ uint32_t Bs[2][128][20];

    const GB gb = batch.g[blockIdx.z];
    const int tid  = threadIdx.x;
    const int lane = tid & 31;
    const int warp = tid >> 5;
    const int wm = (warp >> 2) * 64;
    const int wn = (warp & 3) * 32;
    const int row0 = blockIdx.y * 128;
    const int col0 = blockIdx.x * 128;
    const int K1 = gb.K1, Ktot = K1 + gb.K2;
    const int nc = Ktot >> 5;
    const int lr = lane >> 2, lc = lane & 3;

    float acc[4][4][4] = {};

    auto fill = [&](int c, int buf) {
        const int kc0 = c << 5;
        const __half* A; int kc, lda;
        if (kc0 < K1) { A = gb.A1; kc = kc0;      lda = K1; }
        else          { A = gb.A2; kc = kc0 - K1; lda = gb.K2; }
        #pragma unroll
        for (int i = 0; i < 2; i++) {
            int idx = tid + i * 256;
            int r = idx >> 2, ch = idx & 3;
            cp16(&As[buf][r][ch * 4], &A[(size_t)(row0 + r) * lda + kc + ch * 8]);
        }
        #pragma unroll
        for (int i = 0; i < 2; i++) {
            int idx = tid + i * 256;
            int r = idx >> 2, ch = idx & 3;
            cp16(&Bs[buf][r][ch * 4], &gb.Wt[(size_t)(col0 + r) * Ktot + kc0 + ch * 8]);
        }
        asm volatile("cp.async.commit_group;");
    };

    fill(0, 0);
    fill(1, 1);

    for (int c = 0; c < nc; c++) {
        const int buf = c & 1;
        asm volatile("cp.async.wait_group 1;" ::: "memory");
        __syncthreads();

        #pragma unroll
        for (int ks = 0; ks < 2; ks++) {
            uint32_t a[4][4], b[4][2];
            #pragma unroll
            for (int mi = 0; mi < 4; mi++) {
                int m = wm + mi * 16;
                a[mi][0] = As[buf][m + lr    ][ks * 8 + lc    ];
                a[mi][1] = As[buf][m + lr + 8][ks * 8 + lc    ];
                a[mi][2] = As[buf][m + lr    ][ks * 8 + lc + 4];
                a[mi][3] = As[buf][m + lr + 8][ks * 8 + lc + 4];
            }
            #pragma unroll
            for (int ni = 0; ni < 4; ni++) {
                int n = wn + ni * 8;
                b[ni][0] = Bs[buf][n + lr][ks * 8 + lc    ];
                b[ni][1] = Bs[buf][n + lr][ks * 8 + lc + 4];
            }
            #pragma unroll
            for (int mi = 0; mi < 4; mi++)
                #pragma unroll
                for (int ni = 0; ni < 4; ni++)
                    MMA_F16(acc[mi][ni], a[mi], b[ni][0], b[ni][1]);
        }
        __syncthreads();
        if (c + 2 < nc) fill(c + 2, buf);
    }

    const float* bias = gb.bias;
    if (gb.half_out) {
        __half* C = (__half*)gb.C;
        #pragma unroll
        for (int mi = 0; mi < 4; mi++)
            #pragma unroll
            for (int ni = 0; ni < 4; ni++) {
                int r = row0 + wm + mi * 16 + lr;
                int cc = col0 + wn + ni * 8 + lc * 2;
                float b0 = bias[cc], b1 = bias[cc + 1];
                *reinterpret_cast<uint32_t*>(&C[(size_t)r * DIM + cc]) =
                    packf16(acc[mi][ni][0] + b0, acc[mi][ni][1] + b1);
                *reinterpret_cast<uint32_t*>(&C[(size_t)(r + 8) * DIM + cc]) =
                    packf16(acc[mi][ni][2] + b0, acc[mi][ni][3] + b1);
            }
    } else {
        float* C = (float*)gb.C;
        #pragma unroll
        for (int mi = 0; mi < 4; mi++)
            #pragma unroll
            for (int ni = 0; ni < 4; ni++) {
                int r = row0 + wm + mi * 16 + lr;
                int cc = col0 + wn + ni * 8 + lc * 2;
                float b0 = bias[cc], b1 = bias[cc + 1];
                *reinterpret_cast<float2*>(&C[(size_t)r * DIM + cc]) =
                    make_float2(acc[mi][ni][0] + b0, acc[mi][ni][1] + b1);
                *reinterpret_cast<float2*>(&C[(size_t)(r + 8) * DIM + cc]) =
                    make_float2(acc[mi][ni][2] + b0, acc[mi][ni][3] + b1);
            }
    }
}

// ---------------------------------------------------------------------------
// fp16 merged dual-attention. Block 256 thr / 8 warps; warps 0-3 Q1, 4-7 Q2.
// QK: fp16 m16n8k16, Q frags from gmem regs. P stays in registers (C-frag ->
// A-frag identity), V pre-transposed fp16 [b][d][s]. No P smem round-trip.
// ---------------------------------------------------------------------------
struct AttnJob { const __half* Q1; const __half* Q2; const __half* K;
                 const __half* Vt; __half* O1; __half* O2; };
struct AttnBatch2 { AttnJob j[2]; };

__global__ __launch_bounds__(256) void attn_f16(AttnBatch2 batch)
{
    __shared__ uint32_t Ks[2][64][36];   // [kcol][d-pair], 32 data + 4 pad
    __shared__ uint32_t VT[2][64][36];   // [d][k-pair]

    const int tid  = threadIdx.x;
    const int lane = tid & 31;
    const int warp = tid >> 5;
    const int qset = warp >> 2;
    const int wm   = (warp & 3) * 16;
    const int lr = lane >> 2, lc = lane & 3;

    const int qt = blockIdx.x;
    const int h  = blockIdx.y;
    const int b  = blockIdx.z & 7;
    const AttnJob J = batch.j[blockIdx.z >> 3];

    const __half* Qg = (qset == 0 ? J.Q1 : J.Q2)
                       + ((size_t)(b * SEQ + qt * 64)) * DIM + h * DHEAD;
    const __half* Kg = J.K + (size_t)b * SEQ * DIM + h * DHEAD;
    const __half* Vg = J.Vt + ((size_t)(b * DIM + h * DHEAD)) * SEQ;
    __half* Og = (qset == 0 ? J.O1 : J.O2);

    auto issue_kv = [&](int kt, int buf) {
        #pragma unroll
        for (int i = 0; i < 2; i++) {
            int idx = tid + i * 256;
            int r = idx >> 3, ch = idx & 7;
            cp16(&Ks[buf][r][ch * 4], &Kg[(size_t)(kt * 64 + r) * DIM + ch * 8]);
        }
        #pragma unroll
        for (int i = 0; i < 2; i++) {
            int idx = tid + i * 256;
            int r = idx >> 3, ch = idx & 7;
            cp16(&VT[buf][r][ch * 4], &Vg[(size_t)r * SEQ + kt * 64 + ch * 8]);
        }
        asm volatile("cp.async.commit_group;");
    };

    issue_kv(0, 0);
    issue_kv(1, 1);

    // Q A-frags straight from gmem (u32 = fp16 pair along d)
    uint32_t qa[4][4];
    #pragma unroll
    for (int kk = 0; kk < 4; kk++) {
        qa[kk][0] = *reinterpret_cast<const uint32_t*>(&Qg[(size_t)(wm + lr    ) * DIM + kk * 16 + 2 * lc    ]);
        qa[kk][1] = *reinterpret_cast<const uint32_t*>(&Qg[(size_t)(wm + lr + 8) * DIM + kk * 16 + 2 * lc    ]);
        qa[kk][2] = *reinterpret_cast<const uint32_t*>(&Qg[(size_t)(wm + lr    ) * DIM + kk * 16 + 2 * lc + 8]);
        qa[kk][3] = *reinterpret_cast<const uint32_t*>(&Qg[(size_t)(wm + lr + 8) * DIM + kk * 16 + 2 * lc + 8]);
    }

    float o[8][4] = {};
    float mrow0 = -1e30f, mrow1 = -1e30f, lrow0 = 0.f, lrow1 = 0.f;
    const float Cs = 0.1803368801f;   // 0.125 * log2(e)

    for (int kt = 0; kt < 8; kt++) {
        const int buf = kt & 1;
        asm volatile("cp.async.wait_group 1;" ::: "memory");
        __syncthreads();

        // S = Q @ K^T  (fp16 k16)
        float sc[8][4] = {};
        #pragma unroll
        for (int kk = 0; kk < 4; kk++)
            #pragma unroll
            for (int ni = 0; ni < 8; ni++) {
                uint32_t b0 = Ks[buf][ni * 8 + lr][kk * 8 + lc    ];
                uint32_t b1 = Ks[buf][ni * 8 + lr][kk * 8 + lc + 4];
                MMA_F16(sc[ni], qa[kk], b0, b1);
            }

        // Online softmax (fp32)
        float rm0 = -1e30f, rm1 = -1e30f;
        #pragma unroll
        for (int ni = 0; ni < 8; ni++) {
            rm0 = fmaxf(rm0, fmaxf(sc[ni][0], sc[ni][1]));
            rm1 = fmaxf(rm1, fmaxf(sc[ni][2], sc[ni][3]));
        }
        rm0 = fmaxf(rm0, __shfl_xor_sync(0xffffffffu, rm0, 1));
        rm0 = fmaxf(rm0, __shfl_xor_sync(0xffffffffu, rm0, 2));
        rm1 = fmaxf(rm1, __shfl_xor_sync(0xffffffffu, rm1, 1));
        rm1 = fmaxf(rm1, __shfl_xor_sync(0xffffffffu, rm1, 2));

        float nm0 = fmaxf(mrow0, rm0), nm1 = fmaxf(mrow1, rm1);
        float corr0 = exp2f((mrow0 - nm0) * Cs);
        float corr1 = exp2f((mrow1 - nm1) * Cs);
        mrow0 = nm0; mrow1 = nm1;

        float s0 = 0.f, s1 = 0.f;
        #pragma unroll
        for (int ni = 0; ni < 8; ni++) {
            sc[ni][0] = exp2f((sc[ni][0] - nm0) * Cs);
            sc[ni][1] = exp2f((sc[ni][1] - nm0) * Cs);
            sc[ni][2] = exp2f((sc[ni][2] - nm1) * Cs);
            sc[ni][3] = exp2f((sc[ni][3] - nm1) * Cs);
            s0 += sc[ni][0] + sc[ni][1];
            s1 += sc[ni][2] + sc[ni][3];
        }
        s0 += __shfl_xor_sync(0xffffffffu, s0, 1);
        s0 += __shfl_xor_sync(0xffffffffu, s0, 2);
        s1 += __shfl_xor_sync(0xffffffffu, s1, 1);
        s1 += __shfl_xor_sync(0xffffffffu, s1, 2);
        lrow0 = lrow0 * corr0 + s0;
        lrow1 = lrow1 * corr1 + s1;
        #pragma unroll
        for (int ni = 0; ni < 8; ni++) {
            o[ni][0] *= corr0; o[ni][1] *= corr0;
            o[ni][2] *= corr1; o[ni][3] *= corr1;
        }

        // O += P @ V : P A-frags packed from score registers (no smem!)
        #pragma unroll
        for (int kk = 0; kk < 4; kk++) {
            uint32_t pa[4];
            pa[0] = packf16(sc[2*kk    ][0], sc[2*kk    ][1]);
            pa[1] = packf16(sc[2*kk    ][2], sc[2*kk    ][3]);
            pa[2] = packf16(sc[2*kk + 1][0], sc[2*kk + 1][1]);
            pa[3] = packf16(sc[2*kk + 1][2], sc[2*kk + 1][3]);
            #pragma unroll
            for (int ni = 0; ni < 8; ni++) {
                uint32_t b0 = VT[buf][ni * 8 + lr][kk * 8 + lc    ];
                uint32_t b1 = VT[buf][ni * 8 + lr][kk * 8 + lc + 4];
                MMA_F16(o[ni], pa, b0, b1);
            }
        }
        __syncthreads();
        if (kt + 2 < 8) issue_kv(kt + 2, buf);
    }

    // Epilogue: normalize, fp16 out
    float inv0 = 1.f / lrow0, inv1 = 1.f / lrow1;
    #pragma unroll
    for (int ni = 0; ni < 8; ni++) {
        size_t base = ((size_t)(b * SEQ + qt * 64 + wm + lr)) * DIM + h * DHEAD + ni * 8 + 2 * lc;
        *reinterpret_cast<uint32_t*>(&Og[base]) =
            packf16(o[ni][0] * inv0, o[ni][1] * inv0);
        *reinterpret_cast<uint32_t*>(&Og[base + 8 * DIM]) =
            packf16(o[ni][2] * inv1, o[ni][3] * inv1);
    }
}

// ---------------------------------------------------------------------------
// Host launcher
// ---------------------------------------------------------------------------
extern "C" void kernel_launch(void* const* d_in, const int* in_sizes, int n_in,
                              void* d_out, int out_size)
{
    const float* hs   = (const float*)d_in[0];
    const float* mol  = (const float*)d_in[1];
    const float* Wq   = (const float*)d_in[2];  const float* bq   = (const float*)d_in[3];
    const float* Wk   = (const float*)d_in[4];  const float* bk   = (const float*)d_in[5];
    const float* Wv   = (const float*)d_in[6];  const float* bv   = (const float*)d_in[7];
    const float* Wqm  = (const float*)d_in[8];  const float* bqm  = (const float*)d_in[9];
    const float* Wkm  = (const float*)d_in[10]; const float* bkm  = (const float*)d_in[11];
    const float* Wvm  = (const float*)d_in[12]; const float* bvm  = (const float*)d_in[13];
    const float* Wfc  = (const float*)d_in[14]; const float* bfc  = (const float*)d_in[15];
    const float* Wfcm = (const float*)d_in[16]; const float* bfcm = (const float*)d_in[17];
    const float* Wo   = (const float*)d_in[18]; const float* bo   = (const float*)d_in[19];
    const float* Wom  = (const float*)d_in[20]; const float* bom  = (const float*)d_in[21];

    float* outp = (float*)d_out;
    float* outm = outp + (size_t)MAT;

    float* base = nullptr;
    cudaGetSymbolAddress((void**)&base, g_scratch);
    __half* hb = (__half*)base;
    __half* q    = hb + 0ULL  * MAT;
    __half* k    = hb + 1ULL  * MAT;
    __half* v    = hb + 2ULL  * MAT;
    __half* qm   = hb + 3ULL  * MAT;
    __half* km   = hb + 4ULL  * MAT;
    __half* vm   = hb + 5ULL  * MAT;
    __half* vT   = hb + 6ULL  * MAT;
    __half* vmT  = hb + 7ULL  * MAT;
    __half* app  = hb + 8ULL  * MAT;
    __half* amp  = hb + 9ULL  * MAT;
    __half* amm  = hb + 10ULL * MAT;
    __half* apm  = hb + 11ULL * MAT;
    __half* c1   = hb + 12ULL * MAT;
    __half* c2   = hb + 13ULL * MAT;
    __half* hsr  = hb + 14ULL * MAT;
    __half* molr = hb + 15ULL * MAT;
    __half* wb   = hb + 16ULL * MAT;
    __half* WqT  = wb;
    __half* WkT  = WqT  + W768;
    __half* WvT  = WkT  + W768;
    __half* WqmT = WvT  + W768;
    __half* WkmT = WqmT + W768;
    __half* WvmT = WkmT + W768;
    __half* WoT  = WvmT + W768;
    __half* WomT = WoT  + W768;
    __half* WfcT = WomT + W768;
    __half* WfcmT= WfcT + W1536;

    // 0) Pre-passes
    TBatch tb = {{
        { Wq,  WqT,  768, 768 },  { Wk,  WkT,  768, 768 },
        { Wv,  WvT,  768, 768 },  { Wqm, WqmT, 768, 768 },
        { Wkm, WkmT, 768, 768 },  { Wvm, WvmT, 768, 768 },
        { Wo,  WoT,  768, 768 },  { Wom, WomT, 768, 768 },
        { Wfc, WfcT, 1536, 768 }, { Wfcm, WfcmT, 1536, 768 },
    }};
    transpose_round<<<dim3(48, 24, 10), 256>>>(tb);
    round_copy<<<dim3(MAT / 1024, 2), 256>>>(hs, hsr, mol, molr);

    dim3 gGrid(DIM / 128, ROWS / 128, 1);

    // 1) Six projections -> fp16
    GBatch proj = {{
        { hsr,  nullptr, WqT,  bq,  q,  DIM, 0, 1 },
        { hsr,  nullptr, WkT,  bk,  k,  DIM, 0, 1 },
        { hsr,  nullptr, WvT,  bv,  v,  DIM, 0, 1 },
        { molr, nullptr, WqmT, bqm, qm, DIM, 0, 1 },
        { molr, nullptr, WkmT, bkm, km, DIM, 0, 1 },
        { molr, nullptr, WvmT, bvm, vm, DIM, 0, 1 },
    }};
    gemm_f16<<<dim3(6, 32, 6), 256>>>(proj);

    // 1b) Transpose v, vm for attention B-operand
    transpose_v<<<dim3(12, 8, 16), 256>>>(v, vT, vm, vmT);

    // 2) Merged dual attention
    AttnBatch2 ab = {{
        { q,  qm, k,  vT,  app, amp },
        { qm, q,  km, vmT, amm, apm },
    }};
    attn_f16<<<dim3(SEQ / 64, HEADS, 2 * BATCH), 256>>>(ab);

    // 3) Concat-FC pair (dual-A, K=1536) -> fp16
    GBatch fc = {{
        { app, amp, WfcT,  bfc,  c1, DIM, DIM, 1 },
        { amm, apm, WfcmT, bfcm, c2, DIM, DIM, 1 },
        {}, {}, {}, {},
    }};
    gemm_f16<<<dim3(6, 32, 2), 256>>>(fc);

    // 4) Output projections -> fp32
    GBatch outg = {{
        { c1, nullptr, WoT,  bo,  outp, DIM, 0, 0 },
        { c2, nullptr, WomT, bom, outm, DIM, 0, 0 },
        {}, {}, {}, {},
    }};
    gemm_f16<<<dim3(6, 32, 2), 256>>>(outg);
}

// round 8
// speedup vs baseline: 7.2647x; 1.0115x over previous
#include <cuda_runtime.h>
#include <cuda_fp16.h>
#include <cstdint>

#define BATCH 8
#define SEQ   512
#define DIM   768
#define HEADS 12
#define DHEAD 64
#define ROWS  (BATCH * SEQ)        // 4096
#define MAT   (ROWS * DIM)         // 3145728
#define W768  (768 * 768)
#define W1536 (1536 * 768)

__device__ float g_scratch[17ULL * MAT];

__device__ __forceinline__ uint32_t packf16(float lo, float hi) {
    uint32_t r;
    asm("cvt.rn.f16x2.f32 %0, %1, %2;" : "=r"(r) : "f"(hi), "f"(lo));
    return r;
}

#define MMA_F16(D, A, B0, B1)                                               \
    asm volatile(                                                           \
        "mma.sync.aligned.m16n8k16.row.col.f32.f16.f16.f32 "                \
        "{%0,%1,%2,%3}, {%4,%5,%6,%7}, {%8,%9}, {%0,%1,%2,%3};"             \
        : "+f"((D)[0]), "+f"((D)[1]), "+f"((D)[2]), "+f"((D)[3])            \
        : "r"((A)[0]), "r"((A)[1]), "r"((A)[2]), "r"((A)[3]),               \
          "r"(B0), "r"(B1))

__device__ __forceinline__ void cp16(void* smem_ptr, const void* gptr) {
    uint32_t saddr = (uint32_t)__cvta_generic_to_shared(smem_ptr);
    asm volatile("cp.async.ca.shared.global [%0], [%1], 16;" :: "r"(saddr), "l"(gptr));
}

// ---------------------------------------------------------------------------
// Pre-pass 1: transpose weights to [N,K] fp16
// ---------------------------------------------------------------------------
struct TJ { const float* src; __half* dst; int K; int N; };
struct TBatch { TJ j[10]; };

__global__ __launch_bounds__(256) void transpose_round(TBatch tb)
{
    __shared__ float t[32][33];
    const TJ J = tb.j[blockIdx.z];
    int k0 = blockIdx.x * 32, n0 = blockIdx.y * 32;
    if (k0 >= J.K || n0 >= J.N) return;
    int tx = threadIdx.x & 31, ty = threadIdx.x >> 5;
    #pragma unroll
    for (int i = 0; i < 4; i++)
        t[ty + i * 8][tx] = J.src[(size_t)(k0 + ty + i * 8) * J.N + n0 + tx];
    __syncthreads();
    #pragma unroll
    for (int i = 0; i < 4; i++)
        J.dst[(size_t)(n0 + ty + i * 8) * J.K + k0 + tx] =
            __float2half(t[tx][ty + i * 8]);
}

// Pre-pass 2: fp32 -> fp16 copies of hs, mol
__global__ __launch_bounds__(256) void round_copy(const float* __restrict__ a,
                                                  __half* __restrict__ oa,
                                                  const float* __restrict__ b,
                                                  __half* __restrict__ ob)
{
    size_t i = (size_t)blockIdx.x * 256 + threadIdx.x;
    const float* s = blockIdx.y ? b : a;
    __half* d = blockIdx.y ? ob : oa;
    float4 v = *reinterpret_cast<const float4*>(&s[i * 4]);
    uint2 u = make_uint2(packf16(v.x, v.y), packf16(v.z, v.w));
    *reinterpret_cast<uint2*>(&d[i * 4]) = u;
}

// Pre-pass 3: transpose v, vm (fp16 [b][s][768]) -> vT [b][768][512]
__global__ __launch_bounds__(256) void transpose_v(
    const __half* __restrict__ v, __half* __restrict__ vt,
    const __half* __restrict__ vm, __half* __restrict__ vmt)
{
    __shared__ __half t[64][72];
    const int dt = blockIdx.x * 64, st = blockIdx.y * 64;
    const int b = blockIdx.z & 7;
    const __half* src = (blockIdx.z >> 3) ? vm : v;
    __half* dst = (blockIdx.z >> 3) ? vmt : vt;
    const int tid = threadIdx.x;
    #pragma unroll
    for (int i = 0; i < 8; i++) {
        int idx = tid + i * 256;
        int r = idx >> 5, w = idx & 31;
        *reinterpret_cast<uint32_t*>(&t[r][w * 2]) =
            *reinterpret_cast<const uint32_t*>(&src[((size_t)(b * SEQ + st + r)) * DIM + dt + w * 2]);
    }
    __syncthreads();
    #pragma unroll
    for (int i = 0; i < 8; i++) {
        int idx = tid + i * 256;
        int r = idx >> 5, w = idx & 31;
        __half2 p = __halves2half2(t[w * 2][r], t[w * 2 + 1][r]);
        *reinterpret_cast<__half2*>(&dst[((size_t)(b * DIM + dt + r)) * SEQ + st + w * 2]) = p;
    }
}

// ---------------------------------------------------------------------------
// fp16 GEMM (R6 known-good fragment loads): C = A1|A2 @ Wt^T + bias.
// Block 128x128, BK=32, 8 warps (2x4), smem stride 20 words.
// ---------------------------------------------------------------------------
struct GB { const __half* A1; const __half* A2; const __half* Wt; const float* bias;
            void* C; int K1; int K2; int half_out; };
struct GBatch { GB g[6]; };

__global__ __launch_bounds__(256) void gemm_f16(GBatch batch)
{
    __shared__ uint32_t As[2][128][20];
    __shared__ uint32_t Bs[2][128][20];

    const GB gb = batch.g[blockIdx.z];
    const int tid  = threadIdx.x;
    const int lane = tid & 31;
    const int warp = tid >> 5;
    const int wm = (warp >> 2) * 64;
    const int wn = (warp & 3) * 32;
    const int row0 = blockIdx.y * 128;
    const int col0 = blockIdx.x * 128;
    const int K1 = gb.K1, Ktot = K1 + gb.K2;
    const int nc = Ktot >> 5;
    const int lr = lane >> 2, lc = lane & 3;

    float acc[4][4][4] = {};

    auto fill = [&](int c, int buf) {
        const int kc0 = c << 5;
        const __half* A; int kc, lda;
        if (kc0 < K1) { A = gb.A1; kc = kc0;      lda = K1; }
        else          { A = gb.A2; kc = kc0 - K1; lda = gb.K2; }
        #pragma unroll
        for (int i = 0; i < 2; i++) {
            int idx = tid + i * 256;
            int r = idx >> 2, ch = idx & 3;
            cp16(&As[buf][r][ch * 4], &A[(size_t)(row0 + r) * lda + kc + ch * 8]);
        }
        #pragma unroll
        for (int i = 0; i < 2; i++) {
            int idx = tid + i * 256;
            int r = idx >> 2, ch = idx & 3;
            cp16(&Bs[buf][r][ch * 4], &gb.Wt[(size_t)(col0 + r) * Ktot + kc0 + ch * 8]);
        }
        asm volatile("cp.async.commit_group;");
    };

    fill(0, 0);
    fill(1, 1);

    for (int c = 0; c < nc; c++) {
        const int buf = c & 1;
        asm volatile("cp.async.wait_group 1;" ::: "memory");
        __syncthreads();

        #pragma unroll
        for (int ks = 0; ks < 2; ks++) {
            uint32_t a[4][4], b[4][2];
            #pragma unroll
            for (int mi = 0; mi < 4; mi++) {
                int m = wm + mi * 16;
                a[mi][0] = As[buf][m + lr    ][ks * 8 + lc    ];
                a[mi][1] = As[buf][m + lr + 8][ks * 8 + lc    ];
                a[mi][2] = As[buf][m + lr    ][ks * 8 + lc + 4];
                a[mi][3] = As[buf][m + lr + 8][ks * 8 + lc + 4];
            }
            #pragma unroll
            for (int ni = 0; ni < 4; ni++) {
                int n = wn + ni * 8;
                b[ni][0] = Bs[buf][n + lr][ks * 8 + lc    ];
                b[ni][1] = Bs[buf][n + lr][ks * 8 + lc + 4];
            }
            #pragma unroll
            for (int mi = 0; mi < 4; mi++)
                #pragma unroll
                for (int ni = 0; ni < 4; ni++)
                    MMA_F16(acc[mi][ni], a[mi], b[ni][0], b[ni][1]);
        }
        __syncthreads();
        if (c + 2 < nc) fill(c + 2, buf);
    }

    const float* bias = gb.bias;
    if (gb.half_out) {
        __half* C = (__half*)gb.C;
        #pragma unroll
        for (int mi = 0; mi < 4; mi++)
            #pragma unroll
            for (int ni = 0; ni < 4; ni++) {
                int r = row0 + wm + mi * 16 + lr;
                int cc = col0 + wn + ni * 8 + lc * 2;
                float b0 = bias[cc], b1 = bias[cc + 1];
                *reinterpret_cast<uint32_t*>(&C[(size_t)r * DIM + cc]) =
                    packf16(acc[mi][ni][0] + b0, acc[mi][ni][1] + b1);
                *reinterpret_cast<uint32_t*>(&C[(size_t)(r + 8) * DIM + cc]) =
                    packf16(acc[mi][ni][2] + b0, acc[mi][ni][3] + b1);
            }
    } else {
        float* C = (float*)gb.C;
        #pragma unroll
        for (int mi = 0; mi < 4; mi++)
            #pragma unroll
            for (int ni = 0; ni < 4; ni++) {
                int r = row0 + wm + mi * 16 + lr;
                int cc = col0 + wn + ni * 8 + lc * 2;
                float b0 = bias[cc], b1 = bias[cc + 1];
                *reinterpret_cast<float2*>(&C[(size_t)r * DIM + cc]) =
                    make_float2(acc[mi][ni][0] + b0, acc[mi][ni][1] + b1);
                *reinterpret_cast<float2*>(&C[(size_t)(r + 8) * DIM + cc]) =
                    make_float2(acc[mi][ni][2] + b0, acc[mi][ni][3] + b1);
            }
    }
}

// ---------------------------------------------------------------------------
// fp16 merged dual-attention (R6 loads) + f16x2 softmax exp.
// ---------------------------------------------------------------------------
struct AttnJob { const __half* Q1; const __half* Q2; const __half* K;
                 const __half* Vt; __half* O1; __half* O2; };
struct AttnBatch2 { AttnJob j[2]; };

__global__ __launch_bounds__(256) void attn_f16(AttnBatch2 batch)
{
    __shared__ uint32_t Ks[2][64][36];
    __shared__ uint32_t VT[2][64][36];

    const int tid  = threadIdx.x;
    const int lane = tid & 31;
    const int warp = tid >> 5;
    const int qset = warp >> 2;
    const int wm   = (warp & 3) * 16;
    const int lr = lane >> 2, lc = lane & 3;

    const int qt = blockIdx.x;
    const int h  = blockIdx.y;
    const int b  = blockIdx.z & 7;
    const AttnJob J = batch.j[blockIdx.z >> 3];

    const __half* Qg = (qset == 0 ? J.Q1 : J.Q2)
                       + ((size_t)(b * SEQ + qt * 64)) * DIM + h * DHEAD;
    const __half* Kg = J.K + (size_t)b * SEQ * DIM + h * DHEAD;
    const __half* Vg = J.Vt + ((size_t)(b * DIM + h * DHEAD)) * SEQ;
    __half* Og = (qset == 0 ? J.O1 : J.O2);

    auto issue_kv = [&](int kt, int buf) {
        #pragma unroll
        for (int i = 0; i < 2; i++) {
            int idx = tid + i * 256;
            int r = idx >> 3, ch = idx & 7;
            cp16(&Ks[buf][r][ch * 4], &Kg[(size_t)(kt * 64 + r) * DIM + ch * 8]);
        }
        #pragma unroll
        for (int i = 0; i < 2; i++) {
            int idx = tid + i * 256;
            int r = idx >> 3, ch = idx & 7;
            cp16(&VT[buf][r][ch * 4], &Vg[(size_t)r * SEQ + kt * 64 + ch * 8]);
        }
        asm volatile("cp.async.commit_group;");
    };

    issue_kv(0, 0);
    issue_kv(1, 1);

    // Q A-frags from gmem
    uint32_t qa[4][4];
    #pragma unroll
    for (int kk = 0; kk < 4; kk++) {
        qa[kk][0] = *reinterpret_cast<const uint32_t*>(&Qg[(size_t)(wm + lr    ) * DIM + kk * 16 + 2 * lc    ]);
        qa[kk][1] = *reinterpret_cast<const uint32_t*>(&Qg[(size_t)(wm + lr + 8) * DIM + kk * 16 + 2 * lc    ]);
        qa[kk][2] = *reinterpret_cast<const uint32_t*>(&Qg[(size_t)(wm + lr    ) * DIM + kk * 16 + 2 * lc + 8]);
        qa[kk][3] = *reinterpret_cast<const uint32_t*>(&Qg[(size_t)(wm + lr + 8) * DIM + kk * 16 + 2 * lc + 8]);
    }

    float o[8][4] = {};
    float mrow0 = -1e30f, mrow1 = -1e30f, lrow0 = 0.f, lrow1 = 0.f;
    const float Cs = 0.1803368801f;   // 0.125 * log2(e)

    for (int kt = 0; kt < 8; kt++) {
        const int buf = kt & 1;
        asm volatile("cp.async.wait_group 1;" ::: "memory");
        __syncthreads();

        // S = Q @ K^T
        float sc[8][4] = {};
        #pragma unroll
        for (int kk = 0; kk < 4; kk++)
            #pragma unroll
            for (int ni = 0; ni < 8; ni++) {
                uint32_t b0 = Ks[buf][ni * 8 + lr][kk * 8 + lc    ];
                uint32_t b1 = Ks[buf][ni * 8 + lr][kk * 8 + lc + 4];
                MMA_F16(sc[ni], qa[kk], b0, b1);
            }

        // Online softmax: max in fp32, exp via ex2.approx.f16x2 (half MUFU),
        // p stays fp16x2 = PV A-fragments directly; sums in fp32.
        float rm0 = -1e30f, rm1 = -1e30f;
        #pragma unroll
        for (int ni = 0; ni < 8; ni++) {
            rm0 = fmaxf(rm0, fmaxf(sc[ni][0], sc[ni][1]));
            rm1 = fmaxf(rm1, fmaxf(sc[ni][2], sc[ni][3]));
        }
        rm0 = fmaxf(rm0, __shfl_xor_sync(0xffffffffu, rm0, 1));
        rm0 = fmaxf(rm0, __shfl_xor_sync(0xffffffffu, rm0, 2));
        rm1 = fmaxf(rm1, __shfl_xor_sync(0xffffffffu, rm1, 1));
        rm1 = fmaxf(rm1, __shfl_xor_sync(0xffffffffu, rm1, 2));

        float nm0 = fmaxf(mrow0, rm0), nm1 = fmaxf(mrow1, rm1);
        float corr0 = exp2f((mrow0 - nm0) * Cs);
        float corr1 = exp2f((mrow1 - nm1) * Cs);
        mrow0 = nm0; mrow1 = nm1;
        const float c0f = -nm0 * Cs, c1f = -nm1 * Cs;

        uint32_t pe[8][2];
        float s0 = 0.f, s1 = 0.f;
        #pragma unroll
        for (int ni = 0; ni < 8; ni++) {
            float t0 = fmaf(sc[ni][0], Cs, c0f);
            float t1 = fmaf(sc[ni][1], Cs, c0f);
            float t2 = fmaf(sc[ni][2], Cs, c1f);
            float t3 = fmaf(sc[ni][3], Cs, c1f);
            uint32_t h01 = packf16(t0, t1);
            uint32_t h23 = packf16(t2, t3);
            uint32_t e01, e23;
            asm("ex2.approx.f16x2 %0, %1;" : "=r"(e01) : "r"(h01));
            asm("ex2.approx.f16x2 %0, %1;" : "=r"(e23) : "r"(h23));
            pe[ni][0] = e01;
            pe[ni][1] = e23;
            float2 f01 = __half22float2(*reinterpret_cast<__half2*>(&e01));
            float2 f23 = __half22float2(*reinterpret_cast<__half2*>(&e23));
            s0 += f01.x + f01.y;
            s1 += f23.x + f23.y;
        }
        s0 += __shfl_xor_sync(0xffffffffu, s0, 1);
        s0 += __shfl_xor_sync(0xffffffffu, s0, 2);
        s1 += __shfl_xor_sync(0xffffffffu, s1, 1);
        s1 += __shfl_xor_sync(0xffffffffu, s1, 2);
        lrow0 = lrow0 * corr0 + s0;
        lrow1 = lrow1 * corr1 + s1;
        #pragma unroll
        for (int ni = 0; ni < 8; ni++) {
            o[ni][0] *= corr0; o[ni][1] *= corr0;
            o[ni][2] *= corr1; o[ni][3] *= corr1;
        }

        // O += P @ V (P fragments = pe, no packing needed)
        #pragma unroll
        for (int kk = 0; kk < 4; kk++) {
            uint32_t pa[4];
            pa[0] = pe[2 * kk    ][0];
            pa[1] = pe[2 * kk    ][1];
            pa[2] = pe[2 * kk + 1][0];
            pa[3] = pe[2 * kk + 1][1];
            #pragma unroll
            for (int ni = 0; ni < 8; ni++) {
                uint32_t b0 = VT[buf][ni * 8 + lr][kk * 8 + lc    ];
                uint32_t b1 = VT[buf][ni * 8 + lr][kk * 8 + lc + 4];
                MMA_F16(o[ni], pa, b0, b1);
            }
        }
        __syncthreads();
        if (kt + 2 < 8) issue_kv(kt + 2, buf);
    }

    // Epilogue
    float inv0 = 1.f / lrow0, inv1 = 1.f / lrow1;
    #pragma unroll
    for (int ni = 0; ni < 8; ni++) {
        size_t base = ((size_t)(b * SEQ + qt * 64 + wm + lr)) * DIM + h * DHEAD + ni * 8 + 2 * lc;
        *reinterpret_cast<uint32_t*>(&Og[base]) =
            packf16(o[ni][0] * inv0, o[ni][1] * inv0);
        *reinterpret_cast<uint32_t*>(&Og[base + 8 * DIM]) =
            packf16(o[ni][2] * inv1, o[ni][3] * inv1);
    }
}

// ---------------------------------------------------------------------------
// Host launcher
// ---------------------------------------------------------------------------
extern "C" void kernel_launch(void* const* d_in, const int* in_sizes, int n_in,
                              void* d_out, int out_size)
{
    const float* hs   = (const float*)d_in[0];
    const float* mol  = (const float*)d_in[1];
    const float* Wq   = (const float*)d_in[2];  const float* bq   = (const float*)d_in[3];
    const float* Wk   = (const float*)d_in[4];  const float* bk   = (const float*)d_in[5];
    const float* Wv   = (const float*)d_in[6];  const float* bv   = (const float*)d_in[7];
    const float* Wqm  = (const float*)d_in[8];  const float* bqm  = (const float*)d_in[9];
    const float* Wkm  = (const float*)d_in[10]; const float* bkm  = (const float*)d_in[11];
    const float* Wvm  = (const float*)d_in[12]; const float* bvm  = (const float*)d_in[13];
    const float* Wfc  = (const float*)d_in[14]; const float* bfc  = (const float*)d_in[15];
    const float* Wfcm = (const float*)d_in[16]; const float* bfcm = (const float*)d_in[17];
    const float* Wo   = (const float*)d_in[18]; const float* bo   = (const float*)d_in[19];
    const float* Wom  = (const float*)d_in[20]; const float* bom  = (const float*)d_in[21];

    float* outp = (float*)d_out;
    float* outm = outp + (size_t)MAT;

    float* base = nullptr;
    cudaGetSymbolAddress((void**)&base, g_scratch);
    __half* hb = (__half*)base;
    __half* q    = hb + 0ULL  * MAT;
    __half* k    = hb + 1ULL  * MAT;
    __half* v    = hb + 2ULL  * MAT;
    __half* qm   = hb + 3ULL  * MAT;
    __half* km   = hb + 4ULL  * MAT;
    __half* vm   = hb + 5ULL  * MAT;
    __half* vT   = hb + 6ULL  * MAT;
    __half* vmT  = hb + 7ULL  * MAT;
    __half* app  = hb + 8ULL  * MAT;
    __half* amp  = hb + 9ULL  * MAT;
    __half* amm  = hb + 10ULL * MAT;
    __half* apm  = hb + 11ULL * MAT;
    __half* c1   = hb + 12ULL * MAT;
    __half* c2   = hb + 13ULL * MAT;
    __half* hsr  = hb + 14ULL * MAT;
    __half* molr = hb + 15ULL * MAT;
    __half* wb   = hb + 16ULL * MAT;
    __half* WqT  = wb;
    __half* WkT  = WqT  + W768;
    __half* WvT  = WkT  + W768;
    __half* WqmT = WvT  + W768;
    __half* WkmT = WqmT + W768;
    __half* WvmT = WkmT + W768;
    __half* WoT  = WvmT + W768;
    __half* WomT = WoT  + W768;
    __half* WfcT = WomT + W768;
    __half* WfcmT= WfcT + W1536;

    // 0) Pre-passes
    TBatch tb = {{
        { Wq,  WqT,  768, 768 },  { Wk,  WkT,  768, 768 },
        { Wv,  WvT,  768, 768 },  { Wqm, WqmT, 768, 768 },
        { Wkm, WkmT, 768, 768 },  { Wvm, WvmT, 768, 768 },
        { Wo,  WoT,  768, 768 },  { Wom, WomT, 768, 768 },
        { Wfc, WfcT, 1536, 768 }, { Wfcm, WfcmT, 1536, 768 },
    }};
    transpose_round<<<dim3(48, 24, 10), 256>>>(tb);
    round_copy<<<dim3(MAT / 1024, 2), 256>>>(hs, hsr, mol, molr);

    // 1) Six projections -> fp16
    GBatch proj = {{
        { hsr,  nullptr, WqT,  bq,  q,  DIM, 0, 1 },
        { hsr,  nullptr, WkT,  bk,  k,  DIM, 0, 1 },
        { hsr,  nullptr, WvT,  bv,  v,  DIM, 0, 1 },
        { molr, nullptr, WqmT, bqm, qm, DIM, 0, 1 },
        { molr, nullptr, WkmT, bkm, km, DIM, 0, 1 },
        { molr, nullptr, WvmT, bvm, vm, DIM, 0, 1 },
    }};
    gemm_f16<<<dim3(6, 32, 6), 256>>>(proj);

    // 1b) Transpose v, vm for attention B-operand
    transpose_v<<<dim3(12, 8, 16), 256>>>(v, vT, vm, vmT);

    // 2) Merged dual attention
    AttnBatch2 ab = {{
        { q,  qm, k,  vT,  app, amp },
        { qm, q,  km, vmT, amm, apm },
    }};
    attn_f16<<<dim3(SEQ / 64, HEADS, 2 * BATCH), 256>>>(ab);

    // 3) Concat-FC pair (dual-A, K=1536) -> fp16
    GBatch fc = {{
        { app, amp, WfcT,  bfc,  c1, DIM, DIM, 1 },
        { amm, apm, WfcmT, bfcm, c2, DIM, DIM, 1 },
        {}, {}, {}, {},
    }};
    gemm_f16<<<dim3(6, 32, 2), 256>>>(fc);

    // 4) Output projections -> fp32
    GBatch outg = {{
        { c1, nullptr, WoT,  bo,  outp, DIM, 0, 0 },
        { c2, nullptr, WomT, bom, outm, DIM, 0, 0 },
        {}, {}, {}, {},
    }};
    gemm_f16<<<dim3(6, 32, 2), 256>>>(outg);
}